// round 1
// baseline (speedup 1.0000x reference)
#include <cuda_runtime.h>
#include <cuda_fp16.h>
#include <math.h>
#include <stdint.h>

#define LMAXX 10
#define NPTS  131072
#define WDIM  512

// ---------------- device scratch (static, allowed) ----------------
__device__ float  g_KTAB[LMAXX+1][LMAXX+1];
__device__ float  g_DFACT[LMAXX+1];
__device__ __half g_act0[NPTS*WDIM];
__device__ __half g_act1[NPTS*WDIM];
__device__ float  g_h0[NPTS*8];
__device__ __half g_cs[NPTS*32];
__device__ __half g_w1T[WDIM*WDIM];
__device__ __half g_w2T[WDIM*WDIM];
__device__ __half g_w3T[WDIM*WDIM];
__device__ __half g_wcT[32*WDIM];
__device__ float  g_bcPad[32];

__constant__ float LAMBERT_C[11] = {
    3.1415926535897927f, 2.0943951023931957f, 0.7853981633974483f, 0.0f,
    -0.13089969389957473f, 0.0f, 0.04908738521234052f, 0.0f,
    -0.024543692606170262f, 0.0f, 0.014317154020265985f};

// ---------------- constants setup (runs every launch, deterministic) ----------------
__global__ void setup_consts_kernel() {
    if (threadIdx.x != 0 || blockIdx.x != 0) return;
    double fact[22];
    fact[0] = 1.0;
    for (int i = 1; i <= 21; i++) fact[i] = fact[i-1] * i;
    for (int l = 0; l <= LMAXX; l++)
        for (int m = 0; m <= l; m++) {
            double K = sqrt((2.0*l + 1.0) / (4.0*M_PI) * fact[l-m] / fact[l+m]);
            g_KTAB[l][m] = (float)(m == 0 ? K : sqrt(2.0) * K);
        }
    double df = 1.0;
    g_DFACT[0] = 1.0f;
    for (int m = 1; m <= LMAXX; m++) { df *= (2.0*m - 1.0); g_DFACT[m] = (float)df; }
}

// ---------------- weight prep: fp32 -> half, transposed [n][k] ----------------
__global__ void prep_weights_kernel(const float* __restrict__ w1, const float* __restrict__ w2,
                                    const float* __restrict__ w3, const float* __restrict__ wc,
                                    const float* __restrict__ bc) {
    int idx = blockIdx.x * blockDim.x + threadIdx.x;
    const int NW = 3 * WDIM * WDIM;      // 786432
    if (idx < NW) {
        int which = idx >> 18;           // / 262144
        int r = idx & (WDIM*WDIM - 1);
        int k = r >> 9, n = r & 511;
        const float* w = (which == 0) ? w1 : (which == 1) ? w2 : w3;
        __half* o = (which == 0) ? g_w1T : (which == 1) ? g_w2T : g_w3T;
        o[n*WDIM + k] = __float2half(w[k*WDIM + n]);
    } else if (idx < NW + 32*WDIM) {
        int r = idx - NW;
        int k = r & 511, n = r >> 9;     // n in 0..31
        g_wcT[n*WDIM + k] = __float2half(n < 27 ? wc[k*27 + n] : 0.0f);
    } else if (idx < NW + 32*WDIM + 32) {
        int n = idx - (NW + 32*WDIM);
        g_bcPad[n] = n < 27 ? bc[n] : 0.0f;
    }
}

// ---------------- SH accumulate (per-point, refs from SMEM) ----------------
__device__ __forceinline__ void sh_accum(float dx, float dy, float dz,
                                         const float* __restrict__ row,
                                         const float* wl, float* acc) {
    float r = sqrtf(dx*dx + dy*dy + dz*dz);
    float inv = 1.0f / fmaxf(r, 1e-12f);
    float x = dx*inv, y = dy*inv, z = dz*inv;
    float c[LMAXX+1], s[LMAXX+1], rp[LMAXX+1];
    c[0] = 1.0f; s[0] = 0.0f; rp[0] = 1.0f;
#pragma unroll
    for (int m = 1; m <= LMAXX; m++) {
        c[m] = x*c[m-1] - y*s[m-1];
        s[m] = x*s[m-1] + y*c[m-1];
        rp[m] = rp[m-1] * r;
    }
#pragma unroll
    for (int m = 0; m <= LMAXX; m++) {
        float Qa = g_DFACT[m];               // Q[m][m]
        {
            float w = g_KTAB[m][m] * Qa * rp[m] * wl[m];
            int b = (m*m + m) * 3;
            if (m == 0) {
                acc[0] += w*row[b]; acc[1] += w*row[b+1]; acc[2] += w*row[b+2];
            } else {
                float wc_ = w*c[m], ws_ = w*s[m];
                acc[0] += wc_*row[b+3*m];   acc[1] += wc_*row[b+3*m+1];   acc[2] += wc_*row[b+3*m+2];
                acc[0] += ws_*row[b-3*m];   acc[1] += ws_*row[b-3*m+1];   acc[2] += ws_*row[b-3*m+2];
            }
        }
        if (m < LMAXX) {
            float Qb = (2.0f*m + 1.0f) * z * Qa;   // Q[m+1][m]
            {
                int l = m + 1;
                float w = g_KTAB[l][m] * Qb * rp[l] * wl[l];
                int b = (l*l + l) * 3;
                if (m == 0) {
                    acc[0] += w*row[b]; acc[1] += w*row[b+1]; acc[2] += w*row[b+2];
                } else {
                    float wc_ = w*c[m], ws_ = w*s[m];
                    acc[0] += wc_*row[b+3*m]; acc[1] += wc_*row[b+3*m+1]; acc[2] += wc_*row[b+3*m+2];
                    acc[0] += ws_*row[b-3*m]; acc[1] += ws_*row[b-3*m+1]; acc[2] += ws_*row[b-3*m+2];
                }
            }
#pragma unroll
            for (int l = m + 2; l <= LMAXX; l++) {
                float Qc = ((2.0f*l - 1.0f) * z * Qb - (float)(l + m - 1) * Qa) / (float)(l - m);
                Qa = Qb; Qb = Qc;
                float w = g_KTAB[l][m] * Qc * rp[l] * wl[l];
                int b = (l*l + l) * 3;
                if (m == 0) {
                    acc[0] += w*row[b]; acc[1] += w*row[b+1]; acc[2] += w*row[b+2];
                } else {
                    float wc_ = w*c[m], ws_ = w*s[m];
                    acc[0] += wc_*row[b+3*m]; acc[1] += wc_*row[b+3*m+1]; acc[2] += wc_*row[b+3*m+2];
                    acc[0] += ws_*row[b-3*m]; acc[1] += ws_*row[b-3*m+1]; acc[2] += ws_*row[b-3*m+2];
                }
            }
        }
    }
}

__device__ __forceinline__ float sigmoidf_(float x) { return 1.0f / (1.0f + expf(-x)); }

// ---------------- physics: SH irradiance/light + outputs + h0 ----------------
// blockDim = 32 (one warp); each CTA handles 32 points; ref_SH rows staged in SMEM.
__global__ void physics_kernel(const float* __restrict__ normals,
                               const float* __restrict__ viewd,
                               const float* __restrict__ feature,
                               const float* __restrict__ refSH,
                               float* __restrict__ out, int N) {
    __shared__ float ss[32 * 363];
    int lane = threadIdx.x;
    int base = blockIdx.x * 32;
    int i = base + lane;

    // coalesced staging of 32 rows (32*363 floats = 2904 float4)
    const float4* src = (const float4*)(refSH + (size_t)base * 363);
    float4* dst = (float4*)ss;
    for (int t = lane; t < (32*363)/4; t += 32) dst[t] = src[t];
    __syncwarp();

    float nx = normals[i*3+0], ny = normals[i*3+1], nz = normals[i*3+2];
    float vx = viewd[i*3+0],   vy = viewd[i*3+1],   vz = viewd[i*3+2];
    float f0 = feature[i*16];
    float rough = fmaxf(f0, 0.0f) + log1pf(expf(-fabsf(f0)));  // stable softplus
    float dotnv = nx*vx + ny*vy + nz*vz;
    float wx = 2.0f*nx*dotnv - vx;
    float wy = 2.0f*ny*dotnv - vy;
    float wz = 2.0f*nz*dotnv - vz;

    const float* myrow = ss + lane * 363;

    float wlA[11];
#pragma unroll
    for (int l = 0; l <= LMAXX; l++) wlA[l] = LAMBERT_C[l];
    float irr[3] = {0.f, 0.f, 0.f};
    sh_accum(nx, ny, nz, myrow, wlA, irr);

    float wlB[11];
#pragma unroll
    for (int l = 0; l <= LMAXX; l++) wlB[l] = expf(-(float)(l*(l+1)) * 0.5f * rough);
    float lig[3] = {0.f, 0.f, 0.f};
    sh_accum(wx, wy, wz, myrow, wlB, lig);

#pragma unroll
    for (int cc = 0; cc < 3; cc++) {
        float ir = fmaxf(irr[cc], 0.0f);
        float li = fmaxf(lig[cc], 0.0f);
        float alb = sigmoidf_(feature[i*16 + 10 + cc]);
        out[(size_t)3*N  + 3*i + cc] = alb;        // albedo
        out[(size_t)6*N  + 3*i + cc] = alb * ir;   // diffuse
        out[(size_t)12*N + 3*i + cc] = li;         // sh_light[0:N] = light
        out[(size_t)15*N + 3*i + cc] = ir;         // sh_light[N:2N] = irradiance
    }
    // h0 = [dot, view(3), normal(3), roughness]
    float* h = g_h0 + (size_t)i * 8;
    h[0] = dotnv; h[1] = vx; h[2] = vy; h[3] = vz;
    h[4] = nx; h[5] = ny; h[6] = nz; h[7] = rough;
}

// ---------------- layer0: h0(8) @ w0(8x512) + b0, relu -> half ----------------
__global__ void layer0_kernel(const float* __restrict__ w0, const float* __restrict__ b0, int N) {
    int idx = blockIdx.x * blockDim.x + threadIdx.x;
    if (idx >= N * WDIM) return;
    int n = idx & 511, row = idx >> 9;
    const float* h = g_h0 + (size_t)row * 8;
    float acc = b0[n];
#pragma unroll
    for (int k = 0; k < 8; k++) acc += h[k] * w0[k*WDIM + n];
    g_act0[idx] = __float2half(fmaxf(acc, 0.0f));
}

// ---------------- mma.sync fp16 GEMM: C[M][NOUT] = relu?(A[M][512] @ BT^T + bias) ----------------
__device__ __forceinline__ void mma16816(float* d, const uint32_t* a, const uint32_t* b) {
    asm volatile(
        "mma.sync.aligned.m16n8k16.row.col.f32.f16.f16.f32 "
        "{%0,%1,%2,%3}, {%4,%5,%6,%7}, {%8,%9}, {%0,%1,%2,%3};\n"
        : "+f"(d[0]), "+f"(d[1]), "+f"(d[2]), "+f"(d[3])
        : "r"(a[0]), "r"(a[1]), "r"(a[2]), "r"(a[3]), "r"(b[0]), "r"(b[1]));
}

template <int BN, int WN, bool RELU>
__global__ void __launch_bounds__(4*WN*32) mlp_gemm_kernel(
    const __half* __restrict__ A,   // [M][512]
    const __half* __restrict__ BT,  // [NOUT][512] (transposed weights)
    const float* __restrict__ bias, // [NOUT]
    __half* __restrict__ C,         // [M][NOUT]
    int M, int NOUT) {
    constexpr int BM = 128, BK = 32, NTH = 4*WN*32;
    __shared__ __half As[BM][BK + 8];
    __shared__ __half Bs[BN][BK + 8];
    int tid = threadIdx.x;
    int warp = tid >> 5, lane = tid & 31;
    int wm = warp & 3, wn = warp >> 2;
    int g = lane >> 2, t4 = lane & 3;
    long rowbase = (long)blockIdx.y * BM;
    int nbase = blockIdx.x * BN;

    float acc[2][4][4];
#pragma unroll
    for (int a_ = 0; a_ < 2; a_++)
#pragma unroll
        for (int b_ = 0; b_ < 4; b_++)
#pragma unroll
            for (int c_ = 0; c_ < 4; c_++) acc[a_][b_][c_] = 0.0f;

    for (int k0 = 0; k0 < WDIM; k0 += BK) {
        __syncthreads();
#pragma unroll 2
        for (int t = tid; t < BM * (BK/8); t += NTH) {
            int r = t >> 2, sgm = t & 3;
            *(uint4*)&As[r][sgm*8] = *(const uint4*)&A[(rowbase + r) * WDIM + k0 + sgm*8];
        }
#pragma unroll 2
        for (int t = tid; t < BN * (BK/8); t += NTH) {
            int r = t >> 2, sgm = t & 3;
            *(uint4*)&Bs[r][sgm*8] = *(const uint4*)&BT[(long)(nbase + r) * WDIM + k0 + sgm*8];
        }
        __syncthreads();
#pragma unroll
        for (int kk = 0; kk < BK; kk += 16) {
            uint32_t a[2][4], b[4][2];
#pragma unroll
            for (int sm_ = 0; sm_ < 2; sm_++) {
                int r = wm*32 + sm_*16;
                a[sm_][0] = *(const uint32_t*)&As[r + g    ][kk + t4*2    ];
                a[sm_][1] = *(const uint32_t*)&As[r + g + 8][kk + t4*2    ];
                a[sm_][2] = *(const uint32_t*)&As[r + g    ][kk + t4*2 + 8];
                a[sm_][3] = *(const uint32_t*)&As[r + g + 8][kk + t4*2 + 8];
            }
#pragma unroll
            for (int j = 0; j < 4; j++) {
                int n = wn*32 + j*8;
                b[j][0] = *(const uint32_t*)&Bs[n + g][kk + t4*2    ];
                b[j][1] = *(const uint32_t*)&Bs[n + g][kk + t4*2 + 8];
            }
#pragma unroll
            for (int sm_ = 0; sm_ < 2; sm_++)
#pragma unroll
                for (int j = 0; j < 4; j++)
                    mma16816(acc[sm_][j], a[sm_], b[j]);
        }
    }

    // epilogue: +bias, optional relu, half2 stores
#pragma unroll
    for (int sm_ = 0; sm_ < 2; sm_++) {
#pragma unroll
        for (int j = 0; j < 4; j++) {
            long r0 = rowbase + wm*32 + sm_*16 + g;
            int c0 = nbase + wn*32 + j*8 + t4*2;
            float bx = bias[c0], by = bias[c0 + 1];
            float v0 = acc[sm_][j][0] + bx;
            float v1 = acc[sm_][j][1] + by;
            float v2 = acc[sm_][j][2] + bx;
            float v3 = acc[sm_][j][3] + by;
            if (RELU) {
                v0 = fmaxf(v0, 0.f); v1 = fmaxf(v1, 0.f);
                v2 = fmaxf(v2, 0.f); v3 = fmaxf(v3, 0.f);
            }
            *(__half2*)&C[r0 * NOUT + c0]       = __floats2half2_rn(v0, v1);
            *(__half2*)&C[(r0 + 8) * NOUT + c0] = __floats2half2_rn(v2, v3);
        }
    }
}

// ---------------- final epilogue: gate, specular, raw_rgb ----------------
__global__ void final_kernel(const float* __restrict__ feature, float* __restrict__ out, int N) {
    int i = blockIdx.x * blockDim.x + threadIdx.x;
    if (i >= N) return;
    const __half* cp = g_cs + (size_t)i * 32;
    float coe[9];
#pragma unroll
    for (int k = 0; k < 9; k++) coe[k] = feature[i*16 + 1 + k];
    float rr = 0.f, gg = 0.f, bb = 0.f;
#pragma unroll
    for (int k = 0; k < 9; k++) {
        rr += __half2float(cp[k])      * coe[k];
        gg += __half2float(cp[9 + k])  * coe[k];
        bb += __half2float(cp[18 + k]) * coe[k];
    }
    float gate[3] = {sigmoidf_(rr), sigmoidf_(gg), sigmoidf_(bb)};
#pragma unroll
    for (int cc = 0; cc < 3; cc++) {
        float spec = sigmoidf_(feature[i*16 + 13 + cc]);
        float light = out[(size_t)12*N + 3*i + cc];
        float specular = spec * light * gate[cc];
        out[(size_t)9*N + 3*i + cc] = specular;                       // specular
        out[3*i + cc] = out[(size_t)6*N + 3*i + cc] + specular;       // raw_rgb = diffuse + specular
    }
}

// ---------------- launch ----------------
extern "C" void kernel_launch(void* const* d_in, const int* in_sizes, int n_in,
                              void* d_out, int out_size) {
    const float* normals = (const float*)d_in[0];
    const float* viewd   = (const float*)d_in[1];
    const float* feature = (const float*)d_in[2];
    const float* refSH   = (const float*)d_in[3];
    const float* w0 = (const float*)d_in[4];
    const float* b0 = (const float*)d_in[5];
    const float* w1 = (const float*)d_in[6];
    const float* b1 = (const float*)d_in[7];
    const float* w2 = (const float*)d_in[8];
    const float* b2 = (const float*)d_in[9];
    const float* w3 = (const float*)d_in[10];
    const float* b3 = (const float*)d_in[11];
    const float* wc = (const float*)d_in[12];
    const float* bc = (const float*)d_in[13];
    int N = in_sizes[0] / 3;
    float* out = (float*)d_out;

    __half *act0, *act1, *w1T, *w2T, *w3T, *wcT, *cs;
    float *bcPad;
    cudaGetSymbolAddress((void**)&act0, g_act0);
    cudaGetSymbolAddress((void**)&act1, g_act1);
    cudaGetSymbolAddress((void**)&w1T, g_w1T);
    cudaGetSymbolAddress((void**)&w2T, g_w2T);
    cudaGetSymbolAddress((void**)&w3T, g_w3T);
    cudaGetSymbolAddress((void**)&wcT, g_wcT);
    cudaGetSymbolAddress((void**)&cs,  g_cs);
    cudaGetSymbolAddress((void**)&bcPad, g_bcPad);

    setup_consts_kernel<<<1, 1>>>();

    int prepTotal = 3*WDIM*WDIM + 32*WDIM + 32;
    prep_weights_kernel<<<(prepTotal + 255)/256, 256>>>(w1, w2, w3, wc, bc);

    physics_kernel<<<N/32, 32>>>(normals, viewd, feature, refSH, out, N);

    layer0_kernel<<<(N*WDIM + 255)/256, 256>>>(w0, b0, N);

    dim3 gg(WDIM/128, N/128);
    mlp_gemm_kernel<128, 4, true><<<gg, 512>>>(act0, w1T, b1, act1, N, WDIM);
    mlp_gemm_kernel<128, 4, true><<<gg, 512>>>(act1, w2T, b2, act0, N, WDIM);
    mlp_gemm_kernel<128, 4, true><<<gg, 512>>>(act0, w3T, b3, act1, N, WDIM);

    mlp_gemm_kernel<32, 1, false><<<dim3(1, N/128), 128>>>(act1, wcT, bcPad, cs, N, 32);

    final_kernel<<<(N + 127)/128, 128>>>(feature, out, N);
}

// round 2
// speedup vs baseline: 1.2504x; 1.2504x over previous
#include <cuda_runtime.h>
#include <cuda_fp16.h>
#include <math.h>
#include <stdint.h>

#define LMAXX 10
#define NPTS  131072
#define WDIM  512

// ---------------- device scratch (static, allowed) ----------------
__device__ float  g_KTAB[LMAXX+1][LMAXX+1];
__device__ float  g_DFACT[LMAXX+1];
__device__ __half g_act0[NPTS*WDIM];
__device__ __half g_act1[NPTS*WDIM];
__device__ float  g_h0[NPTS*8];
__device__ __half g_cs[NPTS*32];
__device__ __half g_w1T[WDIM*WDIM];
__device__ __half g_w2T[WDIM*WDIM];
__device__ __half g_w3T[WDIM*WDIM];
__device__ __half g_wcT[32*WDIM];
__device__ float  g_bcPad[32];

__constant__ float LAMBERT_C[11] = {
    3.1415926535897927f, 2.0943951023931957f, 0.7853981633974483f, 0.0f,
    -0.13089969389957473f, 0.0f, 0.04908738521234052f, 0.0f,
    -0.024543692606170262f, 0.0f, 0.014317154020265985f};

// ---------------- constants setup ----------------
__global__ void setup_consts_kernel() {
    if (threadIdx.x != 0 || blockIdx.x != 0) return;
    double fact[22];
    fact[0] = 1.0;
    for (int i = 1; i <= 21; i++) fact[i] = fact[i-1] * i;
    for (int l = 0; l <= LMAXX; l++)
        for (int m = 0; m <= l; m++) {
            double K = sqrt((2.0*l + 1.0) / (4.0*M_PI) * fact[l-m] / fact[l+m]);
            g_KTAB[l][m] = (float)(m == 0 ? K : sqrt(2.0) * K);
        }
    double df = 1.0;
    g_DFACT[0] = 1.0f;
    for (int m = 1; m <= LMAXX; m++) { df *= (2.0*m - 1.0); g_DFACT[m] = (float)df; }
}

// ---------------- weight prep: fp32 -> half, transposed [n][k] ----------------
__global__ void prep_weights_kernel(const float* __restrict__ w1, const float* __restrict__ w2,
                                    const float* __restrict__ w3, const float* __restrict__ wc,
                                    const float* __restrict__ bc) {
    int idx = blockIdx.x * blockDim.x + threadIdx.x;
    const int NW = 3 * WDIM * WDIM;
    if (idx < NW) {
        int which = idx >> 18;
        int r = idx & (WDIM*WDIM - 1);
        int k = r >> 9, n = r & 511;
        const float* w = (which == 0) ? w1 : (which == 1) ? w2 : w3;
        __half* o = (which == 0) ? g_w1T : (which == 1) ? g_w2T : g_w3T;
        o[n*WDIM + k] = __float2half(w[k*WDIM + n]);
    } else if (idx < NW + 32*WDIM) {
        int r = idx - NW;
        int k = r & 511, n = r >> 9;
        g_wcT[n*WDIM + k] = __float2half(n < 27 ? wc[k*27 + n] : 0.0f);
    } else if (idx < NW + 32*WDIM + 32) {
        int n = idx - (NW + 32*WDIM);
        g_bcPad[n] = n < 27 ? bc[n] : 0.0f;
    }
}

// ---------------- SH accumulate ----------------
__device__ __forceinline__ void sh_accum(float dx, float dy, float dz,
                                         const float* __restrict__ row,
                                         const float* wl, float* acc) {
    float r = sqrtf(dx*dx + dy*dy + dz*dz);
    float inv = 1.0f / fmaxf(r, 1e-12f);
    float x = dx*inv, y = dy*inv, z = dz*inv;
    float c[LMAXX+1], s[LMAXX+1], rp[LMAXX+1];
    c[0] = 1.0f; s[0] = 0.0f; rp[0] = 1.0f;
#pragma unroll
    for (int m = 1; m <= LMAXX; m++) {
        c[m] = x*c[m-1] - y*s[m-1];
        s[m] = x*s[m-1] + y*c[m-1];
        rp[m] = rp[m-1] * r;
    }
#pragma unroll
    for (int m = 0; m <= LMAXX; m++) {
        float Qa = g_DFACT[m];
        {
            float w = g_KTAB[m][m] * Qa * rp[m] * wl[m];
            int b = (m*m + m) * 3;
            if (m == 0) {
                acc[0] += w*row[b]; acc[1] += w*row[b+1]; acc[2] += w*row[b+2];
            } else {
                float wc_ = w*c[m], ws_ = w*s[m];
                acc[0] += wc_*row[b+3*m];   acc[1] += wc_*row[b+3*m+1];   acc[2] += wc_*row[b+3*m+2];
                acc[0] += ws_*row[b-3*m];   acc[1] += ws_*row[b-3*m+1];   acc[2] += ws_*row[b-3*m+2];
            }
        }
        if (m < LMAXX) {
            float Qb = (2.0f*m + 1.0f) * z * Qa;
            {
                int l = m + 1;
                float w = g_KTAB[l][m] * Qb * rp[l] * wl[l];
                int b = (l*l + l) * 3;
                if (m == 0) {
                    acc[0] += w*row[b]; acc[1] += w*row[b+1]; acc[2] += w*row[b+2];
                } else {
                    float wc_ = w*c[m], ws_ = w*s[m];
                    acc[0] += wc_*row[b+3*m]; acc[1] += wc_*row[b+3*m+1]; acc[2] += wc_*row[b+3*m+2];
                    acc[0] += ws_*row[b-3*m]; acc[1] += ws_*row[b-3*m+1]; acc[2] += ws_*row[b-3*m+2];
                }
            }
#pragma unroll
            for (int l = m + 2; l <= LMAXX; l++) {
                float Qc = ((2.0f*l - 1.0f) * z * Qb - (float)(l + m - 1) * Qa) / (float)(l - m);
                Qa = Qb; Qb = Qc;
                float w = g_KTAB[l][m] * Qc * rp[l] * wl[l];
                int b = (l*l + l) * 3;
                if (m == 0) {
                    acc[0] += w*row[b]; acc[1] += w*row[b+1]; acc[2] += w*row[b+2];
                } else {
                    float wc_ = w*c[m], ws_ = w*s[m];
                    acc[0] += wc_*row[b+3*m]; acc[1] += wc_*row[b+3*m+1]; acc[2] += wc_*row[b+3*m+2];
                    acc[0] += ws_*row[b-3*m]; acc[1] += ws_*row[b-3*m+1]; acc[2] += ws_*row[b-3*m+2];
                }
            }
        }
    }
}

__device__ __forceinline__ float sigmoidf_(float x) { return 1.0f / (1.0f + expf(-x)); }

// ---------------- physics ----------------
__global__ void physics_kernel(const float* __restrict__ normals,
                               const float* __restrict__ viewd,
                               const float* __restrict__ feature,
                               const float* __restrict__ refSH,
                               float* __restrict__ out, int N) {
    __shared__ float ss[32 * 363];
    int lane = threadIdx.x;
    int base = blockIdx.x * 32;
    int i = base + lane;

    const float4* src = (const float4*)(refSH + (size_t)base * 363);
    float4* dst = (float4*)ss;
    for (int t = lane; t < (32*363)/4; t += 32) dst[t] = src[t];
    __syncwarp();

    float nx = normals[i*3+0], ny = normals[i*3+1], nz = normals[i*3+2];
    float vx = viewd[i*3+0],   vy = viewd[i*3+1],   vz = viewd[i*3+2];
    float f0 = feature[i*16];
    float rough = fmaxf(f0, 0.0f) + log1pf(expf(-fabsf(f0)));
    float dotnv = nx*vx + ny*vy + nz*vz;
    float wx = 2.0f*nx*dotnv - vx;
    float wy = 2.0f*ny*dotnv - vy;
    float wz = 2.0f*nz*dotnv - vz;

    const float* myrow = ss + lane * 363;

    float wlA[11];
#pragma unroll
    for (int l = 0; l <= LMAXX; l++) wlA[l] = LAMBERT_C[l];
    float irr[3] = {0.f, 0.f, 0.f};
    sh_accum(nx, ny, nz, myrow, wlA, irr);

    float wlB[11];
#pragma unroll
    for (int l = 0; l <= LMAXX; l++) wlB[l] = expf(-(float)(l*(l+1)) * 0.5f * rough);
    float lig[3] = {0.f, 0.f, 0.f};
    sh_accum(wx, wy, wz, myrow, wlB, lig);

#pragma unroll
    for (int cc = 0; cc < 3; cc++) {
        float ir = fmaxf(irr[cc], 0.0f);
        float li = fmaxf(lig[cc], 0.0f);
        float alb = sigmoidf_(feature[i*16 + 10 + cc]);
        out[(size_t)3*N  + 3*i + cc] = alb;
        out[(size_t)6*N  + 3*i + cc] = alb * ir;
        out[(size_t)12*N + 3*i + cc] = li;
        out[(size_t)15*N + 3*i + cc] = ir;
    }
    float* h = g_h0 + (size_t)i * 8;
    h[0] = dotnv; h[1] = vx; h[2] = vy; h[3] = vz;
    h[4] = nx; h[5] = ny; h[6] = nz; h[7] = rough;
}

// ---------------- layer0 v2: register-blocked 4 rows x 8 cols / thread ----------------
__global__ void layer0_kernel_v2(const float* __restrict__ w0, const float* __restrict__ b0, int N) {
    // total threads = (N/4) * (512/8); each computes a 4x8 tile of act0
    int t = blockIdx.x * blockDim.x + threadIdx.x;
    int c8 = t & 63;          // column group (8 cols)
    int r4 = t >> 6;          // row group (4 rows)
    if (r4 >= N/4) return;
    int c0 = c8 * 8;
    long r0 = (long)r4 * 4;

    // load w0 tile [8 k][8 cols] and bias [8]
    float w[8][8], b[8];
#pragma unroll
    for (int j = 0; j < 8; j++) {
        float4 a = *(const float4*)&w0[j*WDIM + c0];
        float4 bvec = *(const float4*)&w0[j*WDIM + c0 + 4];
        w[j][0]=a.x; w[j][1]=a.y; w[j][2]=a.z; w[j][3]=a.w;
        w[j][4]=bvec.x; w[j][5]=bvec.y; w[j][6]=bvec.z; w[j][7]=bvec.w;
    }
    {
        float4 a = *(const float4*)&b0[c0];
        float4 bvec = *(const float4*)&b0[c0 + 4];
        b[0]=a.x; b[1]=a.y; b[2]=a.z; b[3]=a.w;
        b[4]=bvec.x; b[5]=bvec.y; b[6]=bvec.z; b[7]=bvec.w;
    }

#pragma unroll
    for (int r = 0; r < 4; r++) {
        const float4* hp = (const float4*)(g_h0 + (r0 + r) * 8);
        float4 h01 = hp[0], h23 = hp[1];
        float hh[8] = {h01.x, h01.y, h01.z, h01.w, h23.x, h23.y, h23.z, h23.w};
        __half res[8];
#pragma unroll
        for (int cix = 0; cix < 8; cix++) {
            float acc = b[cix];
#pragma unroll
            for (int j = 0; j < 8; j++) acc += hh[j] * w[j][cix];
            res[cix] = __float2half(fmaxf(acc, 0.0f));
        }
        *(uint4*)&g_act0[(r0 + r) * WDIM + c0] = *(uint4*)res;
    }
}

// ---------------- cp.async helpers ----------------
__device__ __forceinline__ void cp16(void* smem, const void* g) {
    uint32_t s = (uint32_t)__cvta_generic_to_shared(smem);
    asm volatile("cp.async.ca.shared.global [%0], [%1], 16;\n" :: "r"(s), "l"(g));
}
__device__ __forceinline__ void cp_commit() { asm volatile("cp.async.commit_group;\n"); }
__device__ __forceinline__ void cp_wait1() { asm volatile("cp.async.wait_group 1;\n"); }
__device__ __forceinline__ void cp_wait0() { asm volatile("cp.async.wait_group 0;\n"); }

__device__ __forceinline__ void mma16816(float* d, const uint32_t* a, const uint32_t* b) {
    asm volatile(
        "mma.sync.aligned.m16n8k16.row.col.f32.f16.f16.f32 "
        "{%0,%1,%2,%3}, {%4,%5,%6,%7}, {%8,%9}, {%0,%1,%2,%3};\n"
        : "+f"(d[0]), "+f"(d[1]), "+f"(d[2]), "+f"(d[3])
        : "r"(a[0]), "r"(a[1]), "r"(a[2]), "r"(a[3]), "r"(b[0]), "r"(b[1]));
}

// ---------------- double-buffered cp.async HMMA GEMM ----------------
template <int BN, int WN, bool RELU>
__global__ void __launch_bounds__(4*WN*32) mlp_gemm2_kernel(
    const __half* __restrict__ A,   // [M][512]
    const __half* __restrict__ BT,  // [NOUT][512]
    const float* __restrict__ bias, // [NOUT]
    __half* __restrict__ C,         // [M][NOUT]
    int M, int NOUT) {
    constexpr int BM = 128, BK = 32, NTH = 4*WN*32;
    constexpr int LDA = BK + 8;
    __shared__ __half As[2][BM][LDA];
    __shared__ __half Bs[2][BN][LDA];
    int tid = threadIdx.x;
    int warp = tid >> 5, lane = tid & 31;
    int wm = warp & 3, wn = warp >> 2;
    int g = lane >> 2, t4 = lane & 3;
    long rowbase = (long)blockIdx.y * BM;
    int nbase = blockIdx.x * BN;

    float acc[2][4][4];
#pragma unroll
    for (int a_ = 0; a_ < 2; a_++)
#pragma unroll
        for (int b_ = 0; b_ < 4; b_++)
#pragma unroll
            for (int c_ = 0; c_ < 4; c_++) acc[a_][b_][c_] = 0.0f;

    auto load_stage = [&](int buf, int k0) {
#pragma unroll
        for (int t = tid; t < BM * (BK/8); t += NTH) {
            int r = t >> 2, seg = t & 3;
            cp16(&As[buf][r][seg*8], &A[(rowbase + r) * WDIM + k0 + seg*8]);
        }
#pragma unroll
        for (int t = tid; t < BN * (BK/8); t += NTH) {
            int r = t >> 2, seg = t & 3;
            cp16(&Bs[buf][r][seg*8], &BT[(long)(nbase + r) * WDIM + k0 + seg*8]);
        }
        cp_commit();
    };

    constexpr int NS = WDIM / BK;   // 16 stages
    load_stage(0, 0);

    for (int s = 0; s < NS; s++) {
        int cur = s & 1;
        if (s + 1 < NS) {
            load_stage(cur ^ 1, (s + 1) * BK);
            cp_wait1();
        } else {
            cp_wait0();
        }
        __syncthreads();

#pragma unroll
        for (int kk = 0; kk < BK; kk += 16) {
            uint32_t a[2][4], b[4][2];
#pragma unroll
            for (int sm_ = 0; sm_ < 2; sm_++) {
                int r = wm*32 + sm_*16;
                a[sm_][0] = *(const uint32_t*)&As[cur][r + g    ][kk + t4*2    ];
                a[sm_][1] = *(const uint32_t*)&As[cur][r + g + 8][kk + t4*2    ];
                a[sm_][2] = *(const uint32_t*)&As[cur][r + g    ][kk + t4*2 + 8];
                a[sm_][3] = *(const uint32_t*)&As[cur][r + g + 8][kk + t4*2 + 8];
            }
#pragma unroll
            for (int j = 0; j < 4; j++) {
                int n = wn*32 + j*8;
                b[j][0] = *(const uint32_t*)&Bs[cur][n + g][kk + t4*2    ];
                b[j][1] = *(const uint32_t*)&Bs[cur][n + g][kk + t4*2 + 8];
            }
#pragma unroll
            for (int sm_ = 0; sm_ < 2; sm_++)
#pragma unroll
                for (int j = 0; j < 4; j++)
                    mma16816(acc[sm_][j], a[sm_], b[j]);
        }
        __syncthreads();
    }

#pragma unroll
    for (int sm_ = 0; sm_ < 2; sm_++) {
#pragma unroll
        for (int j = 0; j < 4; j++) {
            long r0 = rowbase + wm*32 + sm_*16 + g;
            int c0 = nbase + wn*32 + j*8 + t4*2;
            float bx = bias[c0], by = bias[c0 + 1];
            float v0 = acc[sm_][j][0] + bx;
            float v1 = acc[sm_][j][1] + by;
            float v2 = acc[sm_][j][2] + bx;
            float v3 = acc[sm_][j][3] + by;
            if (RELU) {
                v0 = fmaxf(v0, 0.f); v1 = fmaxf(v1, 0.f);
                v2 = fmaxf(v2, 0.f); v3 = fmaxf(v3, 0.f);
            }
            *(__half2*)&C[r0 * NOUT + c0]       = __floats2half2_rn(v0, v1);
            *(__half2*)&C[(r0 + 8) * NOUT + c0] = __floats2half2_rn(v2, v3);
        }
    }
}

// ---------------- final epilogue ----------------
__global__ void final_kernel(const float* __restrict__ feature, float* __restrict__ out, int N) {
    int i = blockIdx.x * blockDim.x + threadIdx.x;
    if (i >= N) return;
    const __half* cp = g_cs + (size_t)i * 32;
    float coe[9];
#pragma unroll
    for (int k = 0; k < 9; k++) coe[k] = feature[i*16 + 1 + k];
    float rr = 0.f, gg = 0.f, bb = 0.f;
#pragma unroll
    for (int k = 0; k < 9; k++) {
        rr += __half2float(cp[k])      * coe[k];
        gg += __half2float(cp[9 + k])  * coe[k];
        bb += __half2float(cp[18 + k]) * coe[k];
    }
    float gate[3] = {sigmoidf_(rr), sigmoidf_(gg), sigmoidf_(bb)};
#pragma unroll
    for (int cc = 0; cc < 3; cc++) {
        float spec = sigmoidf_(feature[i*16 + 13 + cc]);
        float light = out[(size_t)12*N + 3*i + cc];
        float specular = spec * light * gate[cc];
        out[(size_t)9*N + 3*i + cc] = specular;
        out[3*i + cc] = out[(size_t)6*N + 3*i + cc] + specular;
    }
}

// ---------------- launch ----------------
extern "C" void kernel_launch(void* const* d_in, const int* in_sizes, int n_in,
                              void* d_out, int out_size) {
    const float* normals = (const float*)d_in[0];
    const float* viewd   = (const float*)d_in[1];
    const float* feature = (const float*)d_in[2];
    const float* refSH   = (const float*)d_in[3];
    const float* w0 = (const float*)d_in[4];
    const float* b0 = (const float*)d_in[5];
    const float* w1 = (const float*)d_in[6];
    const float* b1 = (const float*)d_in[7];
    const float* w2 = (const float*)d_in[8];
    const float* b2 = (const float*)d_in[9];
    const float* w3 = (const float*)d_in[10];
    const float* b3 = (const float*)d_in[11];
    const float* wc = (const float*)d_in[12];
    const float* bc = (const float*)d_in[13];
    int N = in_sizes[0] / 3;
    float* out = (float*)d_out;

    __half *act0, *act1, *w1T, *w2T, *w3T, *wcT, *cs;
    float *bcPad;
    cudaGetSymbolAddress((void**)&act0, g_act0);
    cudaGetSymbolAddress((void**)&act1, g_act1);
    cudaGetSymbolAddress((void**)&w1T, g_w1T);
    cudaGetSymbolAddress((void**)&w2T, g_w2T);
    cudaGetSymbolAddress((void**)&w3T, g_w3T);
    cudaGetSymbolAddress((void**)&wcT, g_wcT);
    cudaGetSymbolAddress((void**)&cs,  g_cs);
    cudaGetSymbolAddress((void**)&bcPad, g_bcPad);

    setup_consts_kernel<<<1, 1>>>();

    int prepTotal = 3*WDIM*WDIM + 32*WDIM + 32;
    prep_weights_kernel<<<(prepTotal + 255)/256, 256>>>(w1, w2, w3, wc, bc);

    physics_kernel<<<N/32, 32>>>(normals, viewd, feature, refSH, out, N);

    // layer0 v2: (N/4)*(512/8) threads
    {
        long nth = (long)(N/4) * 64;
        layer0_kernel_v2<<<(unsigned)((nth + 255)/256), 256>>>(w0, b0, N);
    }

    dim3 gg(WDIM/128, N/128);
    mlp_gemm2_kernel<128, 4, true><<<gg, 512>>>(act0, w1T, b1, act1, N, WDIM);
    mlp_gemm2_kernel<128, 4, true><<<gg, 512>>>(act1, w2T, b2, act0, N, WDIM);
    mlp_gemm2_kernel<128, 4, true><<<gg, 512>>>(act0, w3T, b3, act1, N, WDIM);

    mlp_gemm2_kernel<32, 1, false><<<dim3(1, N/128), 128>>>(act1, wcT, bcPad, cs, N, 32);

    final_kernel<<<(N + 127)/128, 128>>>(feature, out, N);
}

// round 6
// speedup vs baseline: 1.3670x; 1.0932x over previous
#include <cuda_runtime.h>
#include <cuda_fp16.h>
#include <math.h>
#include <stdint.h>

#define LMAXX 10
#define NPTS  131072
#define WDIM  512

#if defined(__CUDA_ARCH_FEAT_SM103_ALL) || defined(__CUDA_ARCH_FEAT_SM100_ALL) || defined(__CUDA_ARCH_SPECIFIC__)
#define HAS_TCGEN05 1
#else
#define HAS_TCGEN05 0
#endif

// ---------------- device scratch ----------------
__device__ float  g_KTAB[LMAXX+1][LMAXX+1];
__device__ float  g_DFACT[LMAXX+1];
__device__ __half g_act0[NPTS*WDIM];
__device__ __half g_act1[NPTS*WDIM];
__device__ float  g_h0[NPTS*8];
__device__ __half g_cs[NPTS*32];
__device__ __half g_w1T[WDIM*WDIM];
__device__ __half g_w2T[WDIM*WDIM];
__device__ __half g_w3T[WDIM*WDIM];
__device__ __half g_wcT[32*WDIM];
__device__ float  g_bcPad[32];

__constant__ float LAMBERT_C[11] = {
    3.1415926535897927f, 2.0943951023931957f, 0.7853981633974483f, 0.0f,
    -0.13089969389957473f, 0.0f, 0.04908738521234052f, 0.0f,
    -0.024543692606170262f, 0.0f, 0.014317154020265985f};

// ---------------- common helpers ----------------
__device__ __forceinline__ uint32_t smem_u32(const void* p) {
    uint32_t a;
    asm("{ .reg .u64 t; cvta.to.shared.u64 t, %1; cvt.u32.u64 %0, t; }" : "=r"(a) : "l"(p));
    return a;
}
__device__ __forceinline__ void cp16(uint32_t smem, const void* g) {
    asm volatile("cp.async.ca.shared.global [%0], [%1], 16;\n" :: "r"(smem), "l"(g));
}
__device__ __forceinline__ void cp_commit() { asm volatile("cp.async.commit_group;\n"); }
__device__ __forceinline__ void cp_wait1()  { asm volatile("cp.async.wait_group 1;\n"); }
__device__ __forceinline__ void cp_wait0()  { asm volatile("cp.async.wait_group 0;\n"); }
#define SW128(o) ((o) ^ (((o) >> 3) & 0x70))

__device__ __forceinline__ void mma16816(float* d, const uint32_t* a, const uint32_t* b) {
    asm volatile(
        "mma.sync.aligned.m16n8k16.row.col.f32.f16.f16.f32 "
        "{%0,%1,%2,%3}, {%4,%5,%6,%7}, {%8,%9}, {%0,%1,%2,%3};\n"
        : "+f"(d[0]), "+f"(d[1]), "+f"(d[2]), "+f"(d[3])
        : "r"(a[0]), "r"(a[1]), "r"(a[2]), "r"(a[3]), "r"(b[0]), "r"(b[1]));
}

#if HAS_TCGEN05
__device__ __forceinline__ uint32_t elect1() {
    uint32_t r;
    asm volatile("{\n\t.reg .pred p;\n\telect.sync _|p, 0xFFFFFFFF;\n\tselp.b32 %0,1,0,p;\n\t}" : "=r"(r));
    return r;
}
#define MBAR_INIT(a, c) \
    asm volatile("mbarrier.init.shared.b64 [%0], %1;" :: "r"(a), "r"((uint32_t)(c)) : "memory")
#define MBAR_INVAL(a) \
    asm volatile("mbarrier.inval.shared.b64 [%0];" :: "r"(a) : "memory")
#define MBAR_WAIT(a, ph) do {                                                   \
    uint32_t _m = (a), _p = (ph), _d;                                           \
    asm volatile("{\n\t.reg .pred p;\n\t"                                       \
        "mbarrier.try_wait.parity.acquire.cta.shared::cta.b64 p, [%1], %2;\n\t" \
        "selp.b32 %0,1,0,p;\n\t}" : "=r"(_d) : "r"(_m), "r"(_p) : "memory");    \
    if (!_d) {                                                                  \
        asm volatile("{\n\t.reg .pred P1;\n\t"                                  \
            "WL_%=:\n\t"                                                        \
            "mbarrier.try_wait.parity.acquire.cta.shared::cta.b64 P1, [%0], %1, 0x989680;\n\t" \
            "@P1 bra.uni WD_%=;\n\t"                                            \
            "bra.uni WL_%=;\n\t"                                                \
            "WD_%=:\n\t}" :: "r"(_m), "r"(_p) : "memory");                      \
    }                                                                           \
} while (0)
#define TC_ALLOC(sa, n) \
    asm volatile("tcgen05.alloc.cta_group::1.sync.aligned.shared::cta.b32 [%0], %1;" \
        :: "r"(sa), "r"((uint32_t)(n)) : "memory")
#define TC_DEALLOC(t, n) \
    asm volatile("tcgen05.dealloc.cta_group::1.sync.aligned.b32 %0, %1;" :: "r"(t), "r"((uint32_t)(n)))
#define TC_COMMIT(mb) \
    asm volatile("tcgen05.commit.cta_group::1.mbarrier::arrive::one.shared::cluster.b64 [%0];" \
        :: "r"(mb) : "memory")
#define TC_FENCE_AFTER()  asm volatile("tcgen05.fence::after_thread_sync;" ::: "memory")
#define TC_FENCE_BEFORE() asm volatile("tcgen05.fence::before_thread_sync;" ::: "memory")
#define TC_WAIT_LD()      asm volatile("tcgen05.wait::ld.sync.aligned;" ::: "memory")
#define FENCE_ASYNC_SH()  asm volatile("fence.proxy.async.shared::cta;" ::: "memory")
#define TC_LD_X32(r, ta) \
    asm volatile("tcgen05.ld.sync.aligned.32x32b.x32.b32 " \
        "{%0, %1, %2, %3, %4, %5, %6, %7, %8, %9, %10, %11, %12, %13, %14, %15, " \
        " %16, %17, %18, %19, %20, %21, %22, %23, %24, %25, %26, %27, %28, %29, %30, %31}, [%32];" \
        : "=r"((r)[0]),  "=r"((r)[1]),  "=r"((r)[2]),  "=r"((r)[3]), \
          "=r"((r)[4]),  "=r"((r)[5]),  "=r"((r)[6]),  "=r"((r)[7]), \
          "=r"((r)[8]),  "=r"((r)[9]),  "=r"((r)[10]), "=r"((r)[11]), \
          "=r"((r)[12]), "=r"((r)[13]), "=r"((r)[14]), "=r"((r)[15]), \
          "=r"((r)[16]), "=r"((r)[17]), "=r"((r)[18]), "=r"((r)[19]), \
          "=r"((r)[20]), "=r"((r)[21]), "=r"((r)[22]), "=r"((r)[23]), \
          "=r"((r)[24]), "=r"((r)[25]), "=r"((r)[26]), "=r"((r)[27]), \
          "=r"((r)[28]), "=r"((r)[29]), "=r"((r)[30]), "=r"((r)[31]) \
        : "r"(ta))

__device__ __forceinline__ void mma_f16_ss(uint32_t d, uint64_t ad, uint64_t bd,
                                           uint32_t idesc, uint32_t en) {
    asm volatile("{\n\t.reg .pred p;\n\tsetp.ne.u32 p, %4, 0;\n\t"
        "tcgen05.mma.cta_group::1.kind::f16 [%0], %1, %2, %3, {%5,%5,%5,%5}, p;\n\t}"
        :: "r"(d), "l"(ad), "l"(bd), "r"(idesc), "r"(en), "r"(0u) : "memory");
}
__device__ __forceinline__ uint64_t make_desc_sw128(uint32_t addr) {
    const uint64_t base = (uint64_t(2) << 61) | (uint64_t(1) << 46) |
                          (uint64_t(64) << 32) | (uint64_t(1) << 16);
    return base | ((uint64_t)(addr >> 4) & 0x3FFF);
}
#endif  // HAS_TCGEN05

// ---------------- unified big GEMM: C[M][512] = relu(A[M][512] @ BT^T + bias) ----------------
// 256 threads; tile M=128 x N=128 x K=512 in 8 stages of BK=64. SW128 layout shared by both paths.
#define G_ABUF   (128*128)
#define G_OFFTM  0
#define G_OFFMB  8
#define G_OFFBI  256
#define G_OFFA   1024
#define G_OFFB   (G_OFFA + 2*G_ABUF)
#define G_SMEM   (G_OFFB + 2*G_ABUF)   // 66560

__device__ __forceinline__ void g_load_stage(uint32_t sb, const __half* A, const __half* BT,
                                             long rowbase, int nbase, int tid, int buf, int k0) {
#pragma unroll
    for (int i = 0; i < 4; i++) {
        int t = tid + i * 256;
        int r = t >> 3, c = t & 7;
        uint32_t off = (uint32_t)(r * 128 + c * 16);
        cp16(sb + G_OFFA + buf * G_ABUF + SW128(off), &A[(rowbase + r) * WDIM + k0 + c * 8]);
    }
#pragma unroll
    for (int i = 0; i < 4; i++) {
        int t = tid + i * 256;
        int r = t >> 3, c = t & 7;
        uint32_t off = (uint32_t)(r * 128 + c * 16);
        cp16(sb + G_OFFB + buf * G_ABUF + SW128(off), &BT[(long)(nbase + r) * WDIM + k0 + c * 8]);
    }
    cp_commit();
}

__global__ void __launch_bounds__(256)
gemm_uni_kernel(const __half* __restrict__ A, const __half* __restrict__ BT,
                const float* __restrict__ bias, __half* __restrict__ C, int M) {
    extern __shared__ __align__(1024) char smem[];
    uint32_t sb = smem_u32(smem);
    int tid = threadIdx.x, wid = tid >> 5, lid = tid & 31;
    long rowbase = (long)blockIdx.y * 128;
    int nbase = blockIdx.x * 128;
    float* biasS = (float*)(smem + G_OFFBI);
    for (int i = tid; i < 128; i += 256) biasS[i] = bias[nbase + i];

    constexpr int NS = WDIM / 64;  // 8

#if HAS_TCGEN05
    if (wid == 0) TC_ALLOC(sb + G_OFFTM, 128);
    if (tid == 0) MBAR_INIT(sb + G_OFFMB, 1);
    __syncthreads();
    uint32_t tmem;
    asm volatile("ld.shared.b32 %0, [%1];" : "=r"(tmem) : "r"(sb + G_OFFTM));

    const uint32_t idesc = (1u << 4) | (16u << 17) | (8u << 24);  // f32 acc, f16, N=128, M=128

    g_load_stage(sb, A, BT, rowbase, nbase, tid, 0, 0);
    for (int s = 0; s < NS; s++) {
        int buf = s & 1;
        if (s >= 1) MBAR_WAIT(sb + G_OFFMB, (s - 1) & 1);
        if (s + 1 < NS) { g_load_stage(sb, A, BT, rowbase, nbase, tid, buf ^ 1, (s + 1) * 64); cp_wait1(); }
        else cp_wait0();
        __syncthreads();
        if (wid == 0 && elect1()) {
            FENCE_ASYNC_SH();
            uint64_t ad = make_desc_sw128(sb + G_OFFA + buf * G_ABUF);
            uint64_t bd = make_desc_sw128(sb + G_OFFB + buf * G_ABUF);
#pragma unroll
            for (int k = 0; k < 4; k++)
                mma_f16_ss(tmem, ad + k * 2, bd + k * 2, idesc, (s > 0 || k > 0) ? 1u : 0u);
            TC_COMMIT(sb + G_OFFMB);
        }
    }
    MBAR_WAIT(sb + G_OFFMB, (NS - 1) & 1);
    TC_FENCE_AFTER();

    // epilogue: warp w -> rows (w&3)*32, cols (w>>2)*64
    int sp = wid & 3, ch = wid >> 2;
    uint32_t d[64];
    TC_LD_X32(&d[0],  tmem + ch * 64);
    TC_LD_X32(&d[32], tmem + ch * 64 + 32);
    TC_WAIT_LD();
    TC_FENCE_BEFORE();

    long r = rowbase + sp * 32 + lid;
    __half* crow = C + r * WDIM + nbase + ch * 64;
    const float* bp = biasS + ch * 64;
#pragma unroll
    for (int c0 = 0; c0 < 64; c0 += 8) {
        __half h[8];
#pragma unroll
        for (int j = 0; j < 8; j++)
            h[j] = __float2half(fmaxf(__uint_as_float(d[c0 + j]) + bp[c0 + j], 0.0f));
        *(uint4*)&crow[c0] = *(uint4*)h;
    }
    __syncthreads();
    if (tid == 0) MBAR_INVAL(sb + G_OFFMB);
    __syncthreads();
    if (wid == 0) TC_DEALLOC(tmem, 128);

#else  // ---------------- HMMA fallback ----------------
    __syncthreads();
    int wm = wid & 3, wn = wid >> 2;          // 4 x 2 warp grid: 32-row x 64-col per warp
    int g = lid >> 2, t4 = lid & 3;
    const char* Abase0 = smem + G_OFFA;
    const char* Bbase0 = smem + G_OFFB;

    float acc[2][8][4];
#pragma unroll
    for (int a_ = 0; a_ < 2; a_++)
#pragma unroll
        for (int b_ = 0; b_ < 8; b_++)
#pragma unroll
            for (int c_ = 0; c_ < 4; c_++) acc[a_][b_][c_] = 0.0f;

    g_load_stage(sb, A, BT, rowbase, nbase, tid, 0, 0);
    for (int s = 0; s < NS; s++) {
        int buf = s & 1;
        if (s + 1 < NS) { g_load_stage(sb, A, BT, rowbase, nbase, tid, buf ^ 1, (s + 1) * 64); cp_wait1(); }
        else cp_wait0();
        __syncthreads();
        const char* Ab = Abase0 + buf * G_ABUF;
        const char* Bb = Bbase0 + buf * G_ABUF;
#pragma unroll
        for (int kk = 0; kk < 64; kk += 16) {
            uint32_t a[2][4], b[8][2];
            int kc = (kk + t4 * 2) * 2;        // byte col
#pragma unroll
            for (int sm_ = 0; sm_ < 2; sm_++) {
                int r0 = wm * 32 + sm_ * 16 + g;
                a[sm_][0] = *(const uint32_t*)(Ab + SW128((uint32_t)(r0 * 128 + kc)));
                a[sm_][1] = *(const uint32_t*)(Ab + SW128((uint32_t)((r0 + 8) * 128 + kc)));
                a[sm_][2] = *(const uint32_t*)(Ab + SW128((uint32_t)(r0 * 128 + kc + 16)));
                a[sm_][3] = *(const uint32_t*)(Ab + SW128((uint32_t)((r0 + 8) * 128 + kc + 16)));
            }
#pragma unroll
            for (int j = 0; j < 8; j++) {
                int n0 = wn * 64 + j * 8 + g;
                b[j][0] = *(const uint32_t*)(Bb + SW128((uint32_t)(n0 * 128 + kc)));
                b[j][1] = *(const uint32_t*)(Bb + SW128((uint32_t)(n0 * 128 + kc + 16)));
            }
#pragma unroll
            for (int sm_ = 0; sm_ < 2; sm_++)
#pragma unroll
                for (int j = 0; j < 8; j++)
                    mma16816(acc[sm_][j], a[sm_], b[j]);
        }
        __syncthreads();
    }
#pragma unroll
    for (int sm_ = 0; sm_ < 2; sm_++) {
#pragma unroll
        for (int j = 0; j < 8; j++) {
            long r0 = rowbase + wm * 32 + sm_ * 16 + g;
            int c0 = nbase + wn * 64 + j * 8 + t4 * 2;
            float bx = biasS[c0 - nbase], by = biasS[c0 - nbase + 1];
            float v0 = fmaxf(acc[sm_][j][0] + bx, 0.f);
            float v1 = fmaxf(acc[sm_][j][1] + by, 0.f);
            float v2 = fmaxf(acc[sm_][j][2] + bx, 0.f);
            float v3 = fmaxf(acc[sm_][j][3] + by, 0.f);
            *(__half2*)&C[r0 * WDIM + c0]       = __floats2half2_rn(v0, v1);
            *(__half2*)&C[(r0 + 8) * WDIM + c0] = __floats2half2_rn(v2, v3);
        }
    }
#endif
}

// ---------------- small HMMA GEMM for wc (N=32) ----------------
__global__ void __launch_bounds__(128) wc_gemm_kernel(
    const __half* __restrict__ A, const __half* __restrict__ BT,
    const float* __restrict__ bias, __half* __restrict__ C, int M) {
    constexpr int BM = 128, BK = 32, BN = 32, NTH = 128;
    constexpr int LDA = BK + 8;
    __shared__ __half As[2][BM][LDA];
    __shared__ __half Bs[2][BN][LDA];
    int tid = threadIdx.x;
    int warp = tid >> 5, lane = tid & 31;
    int wm = warp;          // 4 warps stacked over M
    int g = lane >> 2, t4 = lane & 3;
    long rowbase = (long)blockIdx.y * BM;

    float acc[2][4][4];
#pragma unroll
    for (int a_ = 0; a_ < 2; a_++)
#pragma unroll
        for (int b_ = 0; b_ < 4; b_++)
#pragma unroll
            for (int c_ = 0; c_ < 4; c_++) acc[a_][b_][c_] = 0.0f;

    auto load_stage = [&](int buf, int k0) {
#pragma unroll
        for (int t = tid; t < BM * (BK/8); t += NTH) {
            int r = t >> 2, seg = t & 3;
            cp16(smem_u32(&As[buf][r][seg*8]), &A[(rowbase + r) * WDIM + k0 + seg*8]);
        }
#pragma unroll
        for (int t = tid; t < BN * (BK/8); t += NTH) {
            int r = t >> 2, seg = t & 3;
            cp16(smem_u32(&Bs[buf][r][seg*8]), &BT[(long)r * WDIM + k0 + seg*8]);
        }
        cp_commit();
    };

    constexpr int NS = WDIM / BK;
    load_stage(0, 0);
    for (int s = 0; s < NS; s++) {
        int cur = s & 1;
        if (s + 1 < NS) { load_stage(cur ^ 1, (s + 1) * BK); cp_wait1(); }
        else cp_wait0();
        __syncthreads();
#pragma unroll
        for (int kk = 0; kk < BK; kk += 16) {
            uint32_t a[2][4], b[4][2];
#pragma unroll
            for (int sm_ = 0; sm_ < 2; sm_++) {
                int r = wm*32 + sm_*16;
                a[sm_][0] = *(const uint32_t*)&As[cur][r + g    ][kk + t4*2    ];
                a[sm_][1] = *(const uint32_t*)&As[cur][r + g + 8][kk + t4*2    ];
                a[sm_][2] = *(const uint32_t*)&As[cur][r + g    ][kk + t4*2 + 8];
                a[sm_][3] = *(const uint32_t*)&As[cur][r + g + 8][kk + t4*2 + 8];
            }
#pragma unroll
            for (int j = 0; j < 4; j++) {
                int n = j*8;
                b[j][0] = *(const uint32_t*)&Bs[cur][n + g][kk + t4*2    ];
                b[j][1] = *(const uint32_t*)&Bs[cur][n + g][kk + t4*2 + 8];
            }
#pragma unroll
            for (int sm_ = 0; sm_ < 2; sm_++)
#pragma unroll
                for (int j = 0; j < 4; j++)
                    mma16816(acc[sm_][j], a[sm_], b[j]);
        }
        __syncthreads();
    }
#pragma unroll
    for (int sm_ = 0; sm_ < 2; sm_++) {
#pragma unroll
        for (int j = 0; j < 4; j++) {
            long r0 = rowbase + wm*32 + sm_*16 + g;
            int c0 = j*8 + t4*2;
            float v0 = acc[sm_][j][0] + bias[c0];
            float v1 = acc[sm_][j][1] + bias[c0+1];
            float v2 = acc[sm_][j][2] + bias[c0];
            float v3 = acc[sm_][j][3] + bias[c0+1];
            *(__half2*)&C[r0 * BN + c0]       = __floats2half2_rn(v0, v1);
            *(__half2*)&C[(r0 + 8) * BN + c0] = __floats2half2_rn(v2, v3);
        }
    }
}

// ---------------- constants setup ----------------
__global__ void setup_consts_kernel() {
    if (threadIdx.x != 0 || blockIdx.x != 0) return;
    double fact[22];
    fact[0] = 1.0;
    for (int i = 1; i <= 21; i++) fact[i] = fact[i-1] * i;
    for (int l = 0; l <= LMAXX; l++)
        for (int m = 0; m <= l; m++) {
            double K = sqrt((2.0*l + 1.0) / (4.0*M_PI) * fact[l-m] / fact[l+m]);
            g_KTAB[l][m] = (float)(m == 0 ? K : sqrt(2.0) * K);
        }
    double df = 1.0;
    g_DFACT[0] = 1.0f;
    for (int m = 1; m <= LMAXX; m++) { df *= (2.0*m - 1.0); g_DFACT[m] = (float)df; }
}

// ---------------- weight prep ----------------
__global__ void prep_weights_kernel(const float* __restrict__ w1, const float* __restrict__ w2,
                                    const float* __restrict__ w3, const float* __restrict__ wc,
                                    const float* __restrict__ bc) {
    int idx = blockIdx.x * blockDim.x + threadIdx.x;
    const int NW = 3 * WDIM * WDIM;
    if (idx < NW) {
        int which = idx >> 18;
        int r = idx & (WDIM*WDIM - 1);
        int k = r >> 9, n = r & 511;
        const float* w = (which == 0) ? w1 : (which == 1) ? w2 : w3;
        __half* o = (which == 0) ? g_w1T : (which == 1) ? g_w2T : g_w3T;
        o[n*WDIM + k] = __float2half(w[k*WDIM + n]);
    } else if (idx < NW + 32*WDIM) {
        int r = idx - NW;
        int k = r & 511, n = r >> 9;
        g_wcT[n*WDIM + k] = __float2half(n < 27 ? wc[k*27 + n] : 0.0f);
    } else if (idx < NW + 32*WDIM + 32) {
        int n = idx - (NW + 32*WDIM);
        g_bcPad[n] = n < 27 ? bc[n] : 0.0f;
    }
}

// ---------------- SH accumulate ----------------
__device__ __forceinline__ void sh_accum(float dx, float dy, float dz,
                                         const float* __restrict__ row,
                                         const float* wl, float* acc) {
    float r = sqrtf(dx*dx + dy*dy + dz*dz);
    float inv = 1.0f / fmaxf(r, 1e-12f);
    float x = dx*inv, y = dy*inv, z = dz*inv;
    float c[LMAXX+1], s[LMAXX+1], rp[LMAXX+1];
    c[0] = 1.0f; s[0] = 0.0f; rp[0] = 1.0f;
#pragma unroll
    for (int m = 1; m <= LMAXX; m++) {
        c[m] = x*c[m-1] - y*s[m-1];
        s[m] = x*s[m-1] + y*c[m-1];
        rp[m] = rp[m-1] * r;
    }
#pragma unroll
    for (int m = 0; m <= LMAXX; m++) {
        float Qa = g_DFACT[m];
        {
            float w = g_KTAB[m][m] * Qa * rp[m] * wl[m];
            int b = (m*m + m) * 3;
            if (m == 0) {
                acc[0] += w*row[b]; acc[1] += w*row[b+1]; acc[2] += w*row[b+2];
            } else {
                float wc_ = w*c[m], ws_ = w*s[m];
                acc[0] += wc_*row[b+3*m];   acc[1] += wc_*row[b+3*m+1];   acc[2] += wc_*row[b+3*m+2];
                acc[0] += ws_*row[b-3*m];   acc[1] += ws_*row[b-3*m+1];   acc[2] += ws_*row[b-3*m+2];
            }
        }
        if (m < LMAXX) {
            float Qb = (2.0f*m + 1.0f) * z * Qa;
            {
                int l = m + 1;
                float w = g_KTAB[l][m] * Qb * rp[l] * wl[l];
                int b = (l*l + l) * 3;
                if (m == 0) {
                    acc[0] += w*row[b]; acc[1] += w*row[b+1]; acc[2] += w*row[b+2];
                } else {
                    float wc_ = w*c[m], ws_ = w*s[m];
                    acc[0] += wc_*row[b+3*m]; acc[1] += wc_*row[b+3*m+1]; acc[2] += wc_*row[b+3*m+2];
                    acc[0] += ws_*row[b-3*m]; acc[1] += ws_*row[b-3*m+1]; acc[2] += ws_*row[b-3*m+2];
                }
            }
#pragma unroll
            for (int l = m + 2; l <= LMAXX; l++) {
                float Qc = ((2.0f*l - 1.0f) * z * Qb - (float)(l + m - 1) * Qa) / (float)(l - m);
                Qa = Qb; Qb = Qc;
                float w = g_KTAB[l][m] * Qc * rp[l] * wl[l];
                int b = (l*l + l) * 3;
                if (m == 0) {
                    acc[0] += w*row[b]; acc[1] += w*row[b+1]; acc[2] += w*row[b+2];
                } else {
                    float wc_ = w*c[m], ws_ = w*s[m];
                    acc[0] += wc_*row[b+3*m]; acc[1] += wc_*row[b+3*m+1]; acc[2] += wc_*row[b+3*m+2];
                    acc[0] += ws_*row[b-3*m]; acc[1] += ws_*row[b-3*m+1]; acc[2] += ws_*row[b-3*m+2];
                }
            }
        }
    }
}

__device__ __forceinline__ float sigmoidf_(float x) { return 1.0f / (1.0f + expf(-x)); }

// ---------------- physics ----------------
__global__ void physics_kernel(const float* __restrict__ normals,
                               const float* __restrict__ viewd,
                               const float* __restrict__ feature,
                               const float* __restrict__ refSH,
                               float* __restrict__ out, int N) {
    __shared__ float ss[32 * 363];
    int lane = threadIdx.x;
    int base = blockIdx.x * 32;
    int i = base + lane;

    const float4* src = (const float4*)(refSH + (size_t)base * 363);
    float4* dst = (float4*)ss;
    for (int t = lane; t < (32*363)/4; t += 32) dst[t] = src[t];
    __syncwarp();

    float nx = normals[i*3+0], ny = normals[i*3+1], nz = normals[i*3+2];
    float vx = viewd[i*3+0],   vy = viewd[i*3+1],   vz = viewd[i*3+2];
    float f0 = feature[i*16];
    float rough = fmaxf(f0, 0.0f) + log1pf(expf(-fabsf(f0)));
    float dotnv = nx*vx + ny*vy + nz*vz;
    float wx = 2.0f*nx*dotnv - vx;
    float wy = 2.0f*ny*dotnv - vy;
    float wz = 2.0f*nz*dotnv - vz;

    const float* myrow = ss + lane * 363;

    float wlA[11];
#pragma unroll
    for (int l = 0; l <= LMAXX; l++) wlA[l] = LAMBERT_C[l];
    float irr[3] = {0.f, 0.f, 0.f};
    sh_accum(nx, ny, nz, myrow, wlA, irr);

    float wlB[11];
#pragma unroll
    for (int l = 0; l <= LMAXX; l++) wlB[l] = expf(-(float)(l*(l+1)) * 0.5f * rough);
    float lig[3] = {0.f, 0.f, 0.f};
    sh_accum(wx, wy, wz, myrow, wlB, lig);

#pragma unroll
    for (int cc = 0; cc < 3; cc++) {
        float ir = fmaxf(irr[cc], 0.0f);
        float li = fmaxf(lig[cc], 0.0f);
        float alb = sigmoidf_(feature[i*16 + 10 + cc]);
        out[(size_t)3*N  + 3*i + cc] = alb;
        out[(size_t)6*N  + 3*i + cc] = alb * ir;
        out[(size_t)12*N + 3*i + cc] = li;
        out[(size_t)15*N + 3*i + cc] = ir;
    }
    float* h = g_h0 + (size_t)i * 8;
    h[0] = dotnv; h[1] = vx; h[2] = vy; h[3] = vz;
    h[4] = nx; h[5] = ny; h[6] = nz; h[7] = rough;
}

// ---------------- layer0 ----------------
__global__ void layer0_kernel_v2(const float* __restrict__ w0, const float* __restrict__ b0, int N) {
    int t = blockIdx.x * blockDim.x + threadIdx.x;
    int c8 = t & 63;
    int r4 = t >> 6;
    if (r4 >= N/4) return;
    int c0 = c8 * 8;
    long r0 = (long)r4 * 4;

    float w[8][8], b[8];
#pragma unroll
    for (int j = 0; j < 8; j++) {
        float4 a = *(const float4*)&w0[j*WDIM + c0];
        float4 bvec = *(const float4*)&w0[j*WDIM + c0 + 4];
        w[j][0]=a.x; w[j][1]=a.y; w[j][2]=a.z; w[j][3]=a.w;
        w[j][4]=bvec.x; w[j][5]=bvec.y; w[j][6]=bvec.z; w[j][7]=bvec.w;
    }
    {
        float4 a = *(const float4*)&b0[c0];
        float4 bvec = *(const float4*)&b0[c0 + 4];
        b[0]=a.x; b[1]=a.y; b[2]=a.z; b[3]=a.w;
        b[4]=bvec.x; b[5]=bvec.y; b[6]=bvec.z; b[7]=bvec.w;
    }

#pragma unroll
    for (int r = 0; r < 4; r++) {
        const float4* hp = (const float4*)(g_h0 + (r0 + r) * 8);
        float4 h01 = hp[0], h23 = hp[1];
        float hh[8] = {h01.x, h01.y, h01.z, h01.w, h23.x, h23.y, h23.z, h23.w};
        __half res[8];
#pragma unroll
        for (int cix = 0; cix < 8; cix++) {
            float acc = b[cix];
#pragma unroll
            for (int j = 0; j < 8; j++) acc += hh[j] * w[j][cix];
            res[cix] = __float2half(fmaxf(acc, 0.0f));
        }
        *(uint4*)&g_act0[(r0 + r) * WDIM + c0] = *(uint4*)res;
    }
}

// ---------------- final epilogue ----------------
__global__ void final_kernel(const float* __restrict__ feature, float* __restrict__ out, int N) {
    int i = blockIdx.x * blockDim.x + threadIdx.x;
    if (i >= N) return;
    const __half* cp = g_cs + (size_t)i * 32;
    float coe[9];
#pragma unroll
    for (int k = 0; k < 9; k++) coe[k] = feature[i*16 + 1 + k];
    float rr = 0.f, gg = 0.f, bb = 0.f;
#pragma unroll
    for (int k = 0; k < 9; k++) {
        rr += __half2float(cp[k])      * coe[k];
        gg += __half2float(cp[9 + k])  * coe[k];
        bb += __half2float(cp[18 + k]) * coe[k];
    }
    float gate[3] = {sigmoidf_(rr), sigmoidf_(gg), sigmoidf_(bb)};
#pragma unroll
    for (int cc = 0; cc < 3; cc++) {
        float spec = sigmoidf_(feature[i*16 + 13 + cc]);
        float light = out[(size_t)12*N + 3*i + cc];
        float specular = spec * light * gate[cc];
        out[(size_t)9*N + 3*i + cc] = specular;
        out[3*i + cc] = out[(size_t)6*N + 3*i + cc] + specular;
    }
}

// ---------------- launch ----------------
extern "C" void kernel_launch(void* const* d_in, const int* in_sizes, int n_in,
                              void* d_out, int out_size) {
    const float* normals = (const float*)d_in[0];
    const float* viewd   = (const float*)d_in[1];
    const float* feature = (const float*)d_in[2];
    const float* refSH   = (const float*)d_in[3];
    const float* w0 = (const float*)d_in[4];
    const float* b0 = (const float*)d_in[5];
    const float* b1 = (const float*)d_in[7];
    const float* b2 = (const float*)d_in[9];
    const float* b3 = (const float*)d_in[11];
    int N = in_sizes[0] / 3;
    float* out = (float*)d_out;

    __half *act0, *act1, *w1T, *w2T, *w3T, *wcT, *cs;
    float *bcPad;
    cudaGetSymbolAddress((void**)&act0, g_act0);
    cudaGetSymbolAddress((void**)&act1, g_act1);
    cudaGetSymbolAddress((void**)&w1T, g_w1T);
    cudaGetSymbolAddress((void**)&w2T, g_w2T);
    cudaGetSymbolAddress((void**)&w3T, g_w3T);
    cudaGetSymbolAddress((void**)&wcT, g_wcT);
    cudaGetSymbolAddress((void**)&cs,  g_cs);
    cudaGetSymbolAddress((void**)&bcPad, g_bcPad);

    cudaFuncSetAttribute(gemm_uni_kernel, cudaFuncAttributeMaxDynamicSharedMemorySize, G_SMEM);

    setup_consts_kernel<<<1, 1>>>();

    int prepTotal = 3*WDIM*WDIM + 32*WDIM + 32;
    prep_weights_kernel<<<(prepTotal + 255)/256, 256>>>((const float*)d_in[6], (const float*)d_in[8],
                                                        (const float*)d_in[10], (const float*)d_in[12],
                                                        (const float*)d_in[13]);

    physics_kernel<<<N/32, 32>>>(normals, viewd, feature, refSH, out, N);

    {
        long nth = (long)(N/4) * 64;
        layer0_kernel_v2<<<(unsigned)((nth + 255)/256), 256>>>(w0, b0, N);
    }

    dim3 gg(WDIM/128, N/128);
    gemm_uni_kernel<<<gg, 256, G_SMEM>>>(act0, w1T, b1, act1, N);
    gemm_uni_kernel<<<gg, 256, G_SMEM>>>(act1, w2T, b2, act0, N);
    gemm_uni_kernel<<<gg, 256, G_SMEM>>>(act0, w3T, b3, act1, N);

    wc_gemm_kernel<<<dim3(1, N/128), 128>>>(act1, wcT, bcPad, cs, N);

    final_kernel<<<(N + 127)/128, 128>>>(feature, out, N);
}

// round 7
// speedup vs baseline: 1.6857x; 1.2331x over previous
#include <cuda_runtime.h>
#include <cuda_fp16.h>
#include <math.h>
#include <stdint.h>

#define LMAXX 10
#define NPTS  131072
#define WDIM  512

#if defined(__CUDA_ARCH_FEAT_SM103_ALL) || defined(__CUDA_ARCH_FEAT_SM100_ALL) || defined(__CUDA_ARCH_SPECIFIC__)
#define HAS_TCGEN05 1
#else
#define HAS_TCGEN05 0
#endif

// ---------------- device scratch ----------------
__device__ float  g_KTAB[LMAXX+1][LMAXX+1];
__device__ float  g_DFACT[LMAXX+1];
__device__ __half g_act0[NPTS*WDIM];
__device__ __half g_act1[NPTS*WDIM];
__device__ float  g_h0[NPTS*8];
__device__ __half g_cs[NPTS*32];
__device__ __half g_w1T[WDIM*WDIM];
__device__ __half g_w2T[WDIM*WDIM];
__device__ __half g_w3T[WDIM*WDIM];
__device__ __half g_wcT[32*WDIM];
__device__ float  g_bcPad[32];

__constant__ float LAMBERT_C[11] = {
    3.1415926535897927f, 2.0943951023931957f, 0.7853981633974483f, 0.0f,
    -0.13089969389957473f, 0.0f, 0.04908738521234052f, 0.0f,
    -0.024543692606170262f, 0.0f, 0.014317154020265985f};

// ---------------- common helpers ----------------
__device__ __forceinline__ uint32_t smem_u32(const void* p) {
    uint32_t a;
    asm("{ .reg .u64 t; cvta.to.shared.u64 t, %1; cvt.u32.u64 %0, t; }" : "=r"(a) : "l"(p));
    return a;
}
__device__ __forceinline__ void cp16(uint32_t smem, const void* g) {
    asm volatile("cp.async.ca.shared.global [%0], [%1], 16;\n" :: "r"(smem), "l"(g));
}
__device__ __forceinline__ void cp_commit() { asm volatile("cp.async.commit_group;\n"); }
__device__ __forceinline__ void cp_wait1()  { asm volatile("cp.async.wait_group 1;\n"); }
__device__ __forceinline__ void cp_wait0()  { asm volatile("cp.async.wait_group 0;\n"); }
#define SW128(o) ((o) ^ (((o) >> 3) & 0x70))

__device__ __forceinline__ void mma16816(float* d, const uint32_t* a, const uint32_t* b) {
    asm volatile(
        "mma.sync.aligned.m16n8k16.row.col.f32.f16.f16.f32 "
        "{%0,%1,%2,%3}, {%4,%5,%6,%7}, {%8,%9}, {%0,%1,%2,%3};\n"
        : "+f"(d[0]), "+f"(d[1]), "+f"(d[2]), "+f"(d[3])
        : "r"(a[0]), "r"(a[1]), "r"(a[2]), "r"(a[3]), "r"(b[0]), "r"(b[1]));
}
#define LDSM_X4(r, addr) \
    asm volatile("ldmatrix.sync.aligned.m8n8.x4.shared.b16 {%0,%1,%2,%3}, [%4];" \
        : "=r"((r)[0]), "=r"((r)[1]), "=r"((r)[2]), "=r"((r)[3]) : "r"(addr))

#if HAS_TCGEN05
__device__ __forceinline__ uint32_t elect1() {
    uint32_t r;
    asm volatile("{\n\t.reg .pred p;\n\telect.sync _|p, 0xFFFFFFFF;\n\tselp.b32 %0,1,0,p;\n\t}" : "=r"(r));
    return r;
}
#define MBAR_INIT(a, c) \
    asm volatile("mbarrier.init.shared.b64 [%0], %1;" :: "r"(a), "r"((uint32_t)(c)) : "memory")
#define MBAR_INVAL(a) \
    asm volatile("mbarrier.inval.shared.b64 [%0];" :: "r"(a) : "memory")
#define MBAR_WAIT(a, ph) do {                                                   \
    uint32_t _m = (a), _p = (ph), _d;                                           \
    asm volatile("{\n\t.reg .pred p;\n\t"                                       \
        "mbarrier.try_wait.parity.acquire.cta.shared::cta.b64 p, [%1], %2;\n\t" \
        "selp.b32 %0,1,0,p;\n\t}" : "=r"(_d) : "r"(_m), "r"(_p) : "memory");    \
    if (!_d) {                                                                  \
        asm volatile("{\n\t.reg .pred P1;\n\t"                                  \
            "WL_%=:\n\t"                                                        \
            "mbarrier.try_wait.parity.acquire.cta.shared::cta.b64 P1, [%0], %1, 0x989680;\n\t" \
            "@P1 bra.uni WD_%=;\n\t"                                            \
            "bra.uni WL_%=;\n\t"                                                \
            "WD_%=:\n\t}" :: "r"(_m), "r"(_p) : "memory");                      \
    }                                                                           \
} while (0)
#define TC_ALLOC(sa, n) \
    asm volatile("tcgen05.alloc.cta_group::1.sync.aligned.shared::cta.b32 [%0], %1;" \
        :: "r"(sa), "r"((uint32_t)(n)) : "memory")
#define TC_DEALLOC(t, n) \
    asm volatile("tcgen05.dealloc.cta_group::1.sync.aligned.b32 %0, %1;" :: "r"(t), "r"((uint32_t)(n)))
#define TC_COMMIT(mb) \
    asm volatile("tcgen05.commit.cta_group::1.mbarrier::arrive::one.shared::cluster.b64 [%0];" \
        :: "r"(mb) : "memory")
#define TC_FENCE_AFTER()  asm volatile("tcgen05.fence::after_thread_sync;" ::: "memory")
#define TC_FENCE_BEFORE() asm volatile("tcgen05.fence::before_thread_sync;" ::: "memory")
#define TC_WAIT_LD()      asm volatile("tcgen05.wait::ld.sync.aligned;" ::: "memory")
#define FENCE_ASYNC_SH()  asm volatile("fence.proxy.async.shared::cta;" ::: "memory")
#define TC_LD_X32(r, ta) \
    asm volatile("tcgen05.ld.sync.aligned.32x32b.x32.b32 " \
        "{%0, %1, %2, %3, %4, %5, %6, %7, %8, %9, %10, %11, %12, %13, %14, %15, " \
        " %16, %17, %18, %19, %20, %21, %22, %23, %24, %25, %26, %27, %28, %29, %30, %31}, [%32];" \
        : "=r"((r)[0]),  "=r"((r)[1]),  "=r"((r)[2]),  "=r"((r)[3]), \
          "=r"((r)[4]),  "=r"((r)[5]),  "=r"((r)[6]),  "=r"((r)[7]), \
          "=r"((r)[8]),  "=r"((r)[9]),  "=r"((r)[10]), "=r"((r)[11]), \
          "=r"((r)[12]), "=r"((r)[13]), "=r"((r)[14]), "=r"((r)[15]), \
          "=r"((r)[16]), "=r"((r)[17]), "=r"((r)[18]), "=r"((r)[19]), \
          "=r"((r)[20]), "=r"((r)[21]), "=r"((r)[22]), "=r"((r)[23]), \
          "=r"((r)[24]), "=r"((r)[25]), "=r"((r)[26]), "=r"((r)[27]), \
          "=r"((r)[28]), "=r"((r)[29]), "=r"((r)[30]), "=r"((r)[31]) \
        : "r"(ta))

__device__ __forceinline__ void mma_f16_ss(uint32_t d, uint64_t ad, uint64_t bd,
                                           uint32_t idesc, uint32_t en) {
    asm volatile("{\n\t.reg .pred p;\n\tsetp.ne.u32 p, %4, 0;\n\t"
        "tcgen05.mma.cta_group::1.kind::f16 [%0], %1, %2, %3, {%5,%5,%5,%5}, p;\n\t}"
        :: "r"(d), "l"(ad), "l"(bd), "r"(idesc), "r"(en), "r"(0u) : "memory");
}
__device__ __forceinline__ uint64_t make_desc_sw128(uint32_t addr) {
    const uint64_t base = (uint64_t(2) << 61) | (uint64_t(1) << 46) |
                          (uint64_t(64) << 32) | (uint64_t(1) << 16);
    return base | ((uint64_t)(addr >> 4) & 0x3FFF);
}
#endif  // HAS_TCGEN05

// ---------------- unified big GEMM: C[M][512] = relu(A[M][512] @ BT^T + bias) ----------------
// 256 threads; tile M=128 x N=128 x K=512; 3-stage cp.async ring of BK=64 (SW128 layout).
#define G_ABUF   (128*128)
#define G_OFFTM  0
#define G_OFFMB  8
#define G_OFFBI  256
#define G_OFFA   1024
#define G_OFFB   (G_OFFA + 3*G_ABUF)
#define G_SMEM   (G_OFFB + 3*G_ABUF)   // 99328

__device__ __forceinline__ void g_load_stage(uint32_t sb, const __half* A, const __half* BT,
                                             long rowbase, int nbase, int tid, int buf, int k0) {
#pragma unroll
    for (int i = 0; i < 4; i++) {
        int t = tid + i * 256;
        int r = t >> 3, c = t & 7;
        uint32_t off = (uint32_t)(r * 128 + c * 16);
        cp16(sb + G_OFFA + buf * G_ABUF + SW128(off), &A[(rowbase + r) * WDIM + k0 + c * 8]);
    }
#pragma unroll
    for (int i = 0; i < 4; i++) {
        int t = tid + i * 256;
        int r = t >> 3, c = t & 7;
        uint32_t off = (uint32_t)(r * 128 + c * 16);
        cp16(sb + G_OFFB + buf * G_ABUF + SW128(off), &BT[(long)(nbase + r) * WDIM + k0 + c * 8]);
    }
    cp_commit();
}

__global__ void __launch_bounds__(256, 2)
gemm_uni_kernel(const __half* __restrict__ A, const __half* __restrict__ BT,
                const float* __restrict__ bias, __half* __restrict__ C, int M) {
    extern __shared__ __align__(1024) char smem[];
    uint32_t sb = smem_u32(smem);
    int tid = threadIdx.x, wid = tid >> 5, lid = tid & 31;
    long rowbase = (long)blockIdx.y * 128;
    int nbase = blockIdx.x * 128;
    float* biasS = (float*)(smem + G_OFFBI);
    for (int i = tid; i < 128; i += 256) biasS[i] = bias[nbase + i];

    constexpr int NS = WDIM / 64;  // 8

#if HAS_TCGEN05
    if (wid == 0) TC_ALLOC(sb + G_OFFTM, 128);
    if (tid == 0) MBAR_INIT(sb + G_OFFMB, 1);
    __syncthreads();
    uint32_t tmem;
    asm volatile("ld.shared.b32 %0, [%1];" : "=r"(tmem) : "r"(sb + G_OFFTM));

    const uint32_t idesc = (1u << 4) | (16u << 17) | (8u << 24);  // f32 acc, f16, N=128, M=128

    g_load_stage(sb, A, BT, rowbase, nbase, tid, 0, 0);
    for (int s = 0; s < NS; s++) {
        int buf = s & 1;
        if (s >= 1) MBAR_WAIT(sb + G_OFFMB, (s - 1) & 1);
        if (s + 1 < NS) { g_load_stage(sb, A, BT, rowbase, nbase, tid, buf ^ 1, (s + 1) * 64); cp_wait1(); }
        else cp_wait0();
        __syncthreads();
        if (wid == 0 && elect1()) {
            FENCE_ASYNC_SH();
            uint64_t ad = make_desc_sw128(sb + G_OFFA + buf * G_ABUF);
            uint64_t bd = make_desc_sw128(sb + G_OFFB + buf * G_ABUF);
#pragma unroll
            for (int k = 0; k < 4; k++)
                mma_f16_ss(tmem, ad + k * 2, bd + k * 2, idesc, (s > 0 || k > 0) ? 1u : 0u);
            TC_COMMIT(sb + G_OFFMB);
        }
    }
    MBAR_WAIT(sb + G_OFFMB, (NS - 1) & 1);
    TC_FENCE_AFTER();

    int sp = wid & 3, ch = wid >> 2;
    uint32_t d[64];
    TC_LD_X32(&d[0],  tmem + ch * 64);
    TC_LD_X32(&d[32], tmem + ch * 64 + 32);
    TC_WAIT_LD();
    TC_FENCE_BEFORE();

    long r = rowbase + sp * 32 + lid;
    __half* crow = C + r * WDIM + nbase + ch * 64;
    const float* bp = biasS + ch * 64;
#pragma unroll
    for (int c0 = 0; c0 < 64; c0 += 8) {
        __half h[8];
#pragma unroll
        for (int j = 0; j < 8; j++)
            h[j] = __float2half(fmaxf(__uint_as_float(d[c0 + j]) + bp[c0 + j], 0.0f));
        *(uint4*)&crow[c0] = *(uint4*)h;
    }
    __syncthreads();
    if (tid == 0) MBAR_INVAL(sb + G_OFFMB);
    __syncthreads();
    if (wid == 0) TC_DEALLOC(tmem, 128);

#else  // ---------------- HMMA fallback: ldmatrix + 3-stage cp.async ring ----------------
    int wm = wid & 3, wn = wid >> 2;          // 4 x 2 warp grid: 32-row x 64-col per warp
    int g = lid >> 2, t4 = lid & 3;
    int part = lid >> 3, r8 = lid & 7;
    int prow = (part & 1) * 8 + r8;           // row within 16-row ldmatrix group
    int pkb  = (part >> 1) * 16;              // byte offset for k8 half

    float acc[2][8][4];
#pragma unroll
    for (int a_ = 0; a_ < 2; a_++)
#pragma unroll
        for (int b_ = 0; b_ < 8; b_++)
#pragma unroll
            for (int c_ = 0; c_ < 4; c_++) acc[a_][b_][c_] = 0.0f;

    g_load_stage(sb, A, BT, rowbase, nbase, tid, 0, 0);
    g_load_stage(sb, A, BT, rowbase, nbase, tid, 1, 64);
    for (int s = 0; s < NS; s++) {
        if (s + 1 < NS) cp_wait1(); else cp_wait0();
        __syncthreads();
        if (s + 2 < NS) g_load_stage(sb, A, BT, rowbase, nbase, tid, (s + 2) % 3, (s + 2) * 64);

        int buf = s % 3;
        uint32_t sbA = sb + G_OFFA + buf * G_ABUF;
        uint32_t sbB = sb + G_OFFB + buf * G_ABUF;
#pragma unroll
        for (int kk = 0; kk < 64; kk += 16) {
            uint32_t a[2][4], b[4][4];
#pragma unroll
            for (int sm_ = 0; sm_ < 2; sm_++) {
                int row = wm * 32 + sm_ * 16 + prow;
                uint32_t addr = sbA + SW128((uint32_t)(row * 128 + kk * 2 + pkb));
                LDSM_X4(a[sm_], addr);
            }
#pragma unroll
            for (int j2 = 0; j2 < 4; j2++) {
                int row = wn * 64 + j2 * 16 + prow;
                uint32_t addr = sbB + SW128((uint32_t)(row * 128 + kk * 2 + pkb));
                LDSM_X4(b[j2], addr);
            }
#pragma unroll
            for (int sm_ = 0; sm_ < 2; sm_++) {
#pragma unroll
                for (int j2 = 0; j2 < 4; j2++) {
                    uint32_t blo[2] = {b[j2][0], b[j2][2]};
                    uint32_t bhi[2] = {b[j2][1], b[j2][3]};
                    mma16816(acc[sm_][2 * j2],     a[sm_], blo);
                    mma16816(acc[sm_][2 * j2 + 1], a[sm_], bhi);
                }
            }
        }
    }
    __syncthreads();
#pragma unroll
    for (int sm_ = 0; sm_ < 2; sm_++) {
#pragma unroll
        for (int j = 0; j < 8; j++) {
            long r0 = rowbase + wm * 32 + sm_ * 16 + g;
            int c0 = nbase + wn * 64 + j * 8 + t4 * 2;
            float bx = biasS[c0 - nbase], by = biasS[c0 - nbase + 1];
            float v0 = fmaxf(acc[sm_][j][0] + bx, 0.f);
            float v1 = fmaxf(acc[sm_][j][1] + by, 0.f);
            float v2 = fmaxf(acc[sm_][j][2] + bx, 0.f);
            float v3 = fmaxf(acc[sm_][j][3] + by, 0.f);
            *(__half2*)&C[r0 * WDIM + c0]       = __floats2half2_rn(v0, v1);
            *(__half2*)&C[(r0 + 8) * WDIM + c0] = __floats2half2_rn(v2, v3);
        }
    }
#endif
}

// ---------------- small HMMA GEMM for wc (N=32) ----------------
__global__ void __launch_bounds__(128) wc_gemm_kernel(
    const __half* __restrict__ A, const __half* __restrict__ BT,
    const float* __restrict__ bias, __half* __restrict__ C, int M) {
    constexpr int BM = 128, BK = 32, BN = 32, NTH = 128;
    constexpr int LDA = BK + 8;
    __shared__ __half As[2][BM][LDA];
    __shared__ __half Bs[2][BN][LDA];
    int tid = threadIdx.x;
    int warp = tid >> 5, lane = tid & 31;
    int wm = warp;
    int g = lane >> 2, t4 = lane & 3;
    long rowbase = (long)blockIdx.y * BM;

    float acc[2][4][4];
#pragma unroll
    for (int a_ = 0; a_ < 2; a_++)
#pragma unroll
        for (int b_ = 0; b_ < 4; b_++)
#pragma unroll
            for (int c_ = 0; c_ < 4; c_++) acc[a_][b_][c_] = 0.0f;

    auto load_stage = [&](int buf, int k0) {
#pragma unroll
        for (int t = tid; t < BM * (BK/8); t += NTH) {
            int r = t >> 2, seg = t & 3;
            cp16(smem_u32(&As[buf][r][seg*8]), &A[(rowbase + r) * WDIM + k0 + seg*8]);
        }
#pragma unroll
        for (int t = tid; t < BN * (BK/8); t += NTH) {
            int r = t >> 2, seg = t & 3;
            cp16(smem_u32(&Bs[buf][r][seg*8]), &BT[(long)r * WDIM + k0 + seg*8]);
        }
        cp_commit();
    };

    constexpr int NS = WDIM / BK;
    load_stage(0, 0);
    for (int s = 0; s < NS; s++) {
        int cur = s & 1;
        if (s + 1 < NS) { load_stage(cur ^ 1, (s + 1) * BK); cp_wait1(); }
        else cp_wait0();
        __syncthreads();
#pragma unroll
        for (int kk = 0; kk < BK; kk += 16) {
            uint32_t a[2][4], b[4][2];
#pragma unroll
            for (int sm_ = 0; sm_ < 2; sm_++) {
                int r = wm*32 + sm_*16;
                a[sm_][0] = *(const uint32_t*)&As[cur][r + g    ][kk + t4*2    ];
                a[sm_][1] = *(const uint32_t*)&As[cur][r + g + 8][kk + t4*2    ];
                a[sm_][2] = *(const uint32_t*)&As[cur][r + g    ][kk + t4*2 + 8];
                a[sm_][3] = *(const uint32_t*)&As[cur][r + g + 8][kk + t4*2 + 8];
            }
#pragma unroll
            for (int j = 0; j < 4; j++) {
                int n = j*8;
                b[j][0] = *(const uint32_t*)&Bs[cur][n + g][kk + t4*2    ];
                b[j][1] = *(const uint32_t*)&Bs[cur][n + g][kk + t4*2 + 8];
            }
#pragma unroll
            for (int sm_ = 0; sm_ < 2; sm_++)
#pragma unroll
                for (int j = 0; j < 4; j++)
                    mma16816(acc[sm_][j], a[sm_], b[j]);
        }
        __syncthreads();
    }
#pragma unroll
    for (int sm_ = 0; sm_ < 2; sm_++) {
#pragma unroll
        for (int j = 0; j < 4; j++) {
            long r0 = rowbase + wm*32 + sm_*16 + g;
            int c0 = j*8 + t4*2;
            float v0 = acc[sm_][j][0] + bias[c0];
            float v1 = acc[sm_][j][1] + bias[c0+1];
            float v2 = acc[sm_][j][2] + bias[c0];
            float v3 = acc[sm_][j][3] + bias[c0+1];
            *(__half2*)&C[r0 * BN + c0]       = __floats2half2_rn(v0, v1);
            *(__half2*)&C[(r0 + 8) * BN + c0] = __floats2half2_rn(v2, v3);
        }
    }
}

// ---------------- constants setup ----------------
__global__ void setup_consts_kernel() {
    if (threadIdx.x != 0 || blockIdx.x != 0) return;
    double fact[22];
    fact[0] = 1.0;
    for (int i = 1; i <= 21; i++) fact[i] = fact[i-1] * i;
    for (int l = 0; l <= LMAXX; l++)
        for (int m = 0; m <= l; m++) {
            double K = sqrt((2.0*l + 1.0) / (4.0*M_PI) * fact[l-m] / fact[l+m]);
            g_KTAB[l][m] = (float)(m == 0 ? K : sqrt(2.0) * K);
        }
    double df = 1.0;
    g_DFACT[0] = 1.0f;
    for (int m = 1; m <= LMAXX; m++) { df *= (2.0*m - 1.0); g_DFACT[m] = (float)df; }
}

// ---------------- weight prep ----------------
__global__ void prep_weights_kernel(const float* __restrict__ w1, const float* __restrict__ w2,
                                    const float* __restrict__ w3, const float* __restrict__ wc,
                                    const float* __restrict__ bc) {
    int idx = blockIdx.x * blockDim.x + threadIdx.x;
    const int NW = 3 * WDIM * WDIM;
    if (idx < NW) {
        int which = idx >> 18;
        int r = idx & (WDIM*WDIM - 1);
        int k = r >> 9, n = r & 511;
        const float* w = (which == 0) ? w1 : (which == 1) ? w2 : w3;
        __half* o = (which == 0) ? g_w1T : (which == 1) ? g_w2T : g_w3T;
        o[n*WDIM + k] = __float2half(w[k*WDIM + n]);
    } else if (idx < NW + 32*WDIM) {
        int r = idx - NW;
        int k = r & 511, n = r >> 9;
        g_wcT[n*WDIM + k] = __float2half(n < 27 ? wc[k*27 + n] : 0.0f);
    } else if (idx < NW + 32*WDIM + 32) {
        int n = idx - (NW + 32*WDIM);
        g_bcPad[n] = n < 27 ? bc[n] : 0.0f;
    }
}

// ---------------- SH accumulate ----------------
__device__ __forceinline__ void sh_accum(float dx, float dy, float dz,
                                         const float* __restrict__ row,
                                         const float* wl, float* acc) {
    float r = sqrtf(dx*dx + dy*dy + dz*dz);
    float inv = 1.0f / fmaxf(r, 1e-12f);
    float x = dx*inv, y = dy*inv, z = dz*inv;
    float c[LMAXX+1], s[LMAXX+1], rp[LMAXX+1];
    c[0] = 1.0f; s[0] = 0.0f; rp[0] = 1.0f;
#pragma unroll
    for (int m = 1; m <= LMAXX; m++) {
        c[m] = x*c[m-1] - y*s[m-1];
        s[m] = x*s[m-1] + y*c[m-1];
        rp[m] = rp[m-1] * r;
    }
#pragma unroll
    for (int m = 0; m <= LMAXX; m++) {
        float Qa = g_DFACT[m];
        {
            float w = g_KTAB[m][m] * Qa * rp[m] * wl[m];
            int b = (m*m + m) * 3;
            if (m == 0) {
                acc[0] += w*row[b]; acc[1] += w*row[b+1]; acc[2] += w*row[b+2];
            } else {
                float wc_ = w*c[m], ws_ = w*s[m];
                acc[0] += wc_*row[b+3*m];   acc[1] += wc_*row[b+3*m+1];   acc[2] += wc_*row[b+3*m+2];
                acc[0] += ws_*row[b-3*m];   acc[1] += ws_*row[b-3*m+1];   acc[2] += ws_*row[b-3*m+2];
            }
        }
        if (m < LMAXX) {
            float Qb = (2.0f*m + 1.0f) * z * Qa;
            {
                int l = m + 1;
                float w = g_KTAB[l][m] * Qb * rp[l] * wl[l];
                int b = (l*l + l) * 3;
                if (m == 0) {
                    acc[0] += w*row[b]; acc[1] += w*row[b+1]; acc[2] += w*row[b+2];
                } else {
                    float wc_ = w*c[m], ws_ = w*s[m];
                    acc[0] += wc_*row[b+3*m]; acc[1] += wc_*row[b+3*m+1]; acc[2] += wc_*row[b+3*m+2];
                    acc[0] += ws_*row[b-3*m]; acc[1] += ws_*row[b-3*m+1]; acc[2] += ws_*row[b-3*m+2];
                }
            }
#pragma unroll
            for (int l = m + 2; l <= LMAXX; l++) {
                float Qc = ((2.0f*l - 1.0f) * z * Qb - (float)(l + m - 1) * Qa) / (float)(l - m);
                Qa = Qb; Qb = Qc;
                float w = g_KTAB[l][m] * Qc * rp[l] * wl[l];
                int b = (l*l + l) * 3;
                if (m == 0) {
                    acc[0] += w*row[b]; acc[1] += w*row[b+1]; acc[2] += w*row[b+2];
                } else {
                    float wc_ = w*c[m], ws_ = w*s[m];
                    acc[0] += wc_*row[b+3*m]; acc[1] += wc_*row[b+3*m+1]; acc[2] += wc_*row[b+3*m+2];
                    acc[0] += ws_*row[b-3*m]; acc[1] += ws_*row[b-3*m+1]; acc[2] += ws_*row[b-3*m+2];
                }
            }
        }
    }
}

__device__ __forceinline__ float sigmoidf_(float x) { return 1.0f / (1.0f + expf(-x)); }

// ---------------- physics ----------------
__global__ void physics_kernel(const float* __restrict__ normals,
                               const float* __restrict__ viewd,
                               const float* __restrict__ feature,
                               const float* __restrict__ refSH,
                               float* __restrict__ out, int N) {
    __shared__ float ss[32 * 363];
    int lane = threadIdx.x;
    int base = blockIdx.x * 32;
    int i = base + lane;

    const float4* src = (const float4*)(refSH + (size_t)base * 363);
    float4* dst = (float4*)ss;
    for (int t = lane; t < (32*363)/4; t += 32) dst[t] = src[t];
    __syncwarp();

    float nx = normals[i*3+0], ny = normals[i*3+1], nz = normals[i*3+2];
    float vx = viewd[i*3+0],   vy = viewd[i*3+1],   vz = viewd[i*3+2];
    float f0 = feature[i*16];
    float rough = fmaxf(f0, 0.0f) + log1pf(expf(-fabsf(f0)));
    float dotnv = nx*vx + ny*vy + nz*vz;
    float wx = 2.0f*nx*dotnv - vx;
    float wy = 2.0f*ny*dotnv - vy;
    float wz = 2.0f*nz*dotnv - vz;

    const float* myrow = ss + lane * 363;

    float wlA[11];
#pragma unroll
    for (int l = 0; l <= LMAXX; l++) wlA[l] = LAMBERT_C[l];
    float irr[3] = {0.f, 0.f, 0.f};
    sh_accum(nx, ny, nz, myrow, wlA, irr);

    float wlB[11];
#pragma unroll
    for (int l = 0; l <= LMAXX; l++) wlB[l] = expf(-(float)(l*(l+1)) * 0.5f * rough);
    float lig[3] = {0.f, 0.f, 0.f};
    sh_accum(wx, wy, wz, myrow, wlB, lig);

#pragma unroll
    for (int cc = 0; cc < 3; cc++) {
        float ir = fmaxf(irr[cc], 0.0f);
        float li = fmaxf(lig[cc], 0.0f);
        float alb = sigmoidf_(feature[i*16 + 10 + cc]);
        out[(size_t)3*N  + 3*i + cc] = alb;
        out[(size_t)6*N  + 3*i + cc] = alb * ir;
        out[(size_t)12*N + 3*i + cc] = li;
        out[(size_t)15*N + 3*i + cc] = ir;
    }
    float* h = g_h0 + (size_t)i * 8;
    h[0] = dotnv; h[1] = vx; h[2] = vy; h[3] = vz;
    h[4] = nx; h[5] = ny; h[6] = nz; h[7] = rough;
}

// ---------------- layer0 v3: SMEM-staged weights, 4 cols x 32 rows / thread ----------------
__global__ void __launch_bounds__(256) layer0_kernel_v3(
    const float* __restrict__ w0, const float* __restrict__ b0, int N) {
    __shared__ float sw[8 * WDIM];     // 16KB
    __shared__ float sbias[WDIM];      // 2KB
    __shared__ float sh[64 * 8];       // 2KB
    int tid = threadIdx.x;
    long base = (long)blockIdx.x * 64;

    for (int i = tid; i < 8 * WDIM; i += 256) sw[i] = w0[i];
    for (int i = tid; i < WDIM; i += 256) sbias[i] = b0[i];
    for (int i = tid; i < 64 * 8 / 4; i += 256)
        ((float4*)sh)[i] = ((const float4*)(g_h0 + base * 8))[i];
    __syncthreads();

    int c0 = (tid & 127) * 4;     // 4 cols
    int rg = tid >> 7;            // 0..1

    float w[8][4], bb[4];
#pragma unroll
    for (int j = 0; j < 8; j++)
#pragma unroll
        for (int i = 0; i < 4; i++) w[j][i] = sw[j * WDIM + c0 + i];
#pragma unroll
    for (int i = 0; i < 4; i++) bb[i] = sbias[c0 + i];

    for (int r = rg; r < 64; r += 2) {
        const float* hh = sh + r * 8;
        __half res[4];
#pragma unroll
        for (int i = 0; i < 4; i++) {
            float acc = bb[i];
#pragma unroll
            for (int j = 0; j < 8; j++) acc += hh[j] * w[j][i];
            res[i] = __float2half(fmaxf(acc, 0.0f));
        }
        *(uint2*)&g_act0[(base + r) * WDIM + c0] = *(uint2*)res;
    }
}

// ---------------- final epilogue ----------------
__global__ void final_kernel(const float* __restrict__ feature, float* __restrict__ out, int N) {
    int i = blockIdx.x * blockDim.x + threadIdx.x;
    if (i >= N) return;
    const __half* cp = g_cs + (size_t)i * 32;
    float coe[9];
#pragma unroll
    for (int k = 0; k < 9; k++) coe[k] = feature[i*16 + 1 + k];
    float rr = 0.f, gg = 0.f, bb = 0.f;
#pragma unroll
    for (int k = 0; k < 9; k++) {
        rr += __half2float(cp[k])      * coe[k];
        gg += __half2float(cp[9 + k])  * coe[k];
        bb += __half2float(cp[18 + k]) * coe[k];
    }
    float gate[3] = {sigmoidf_(rr), sigmoidf_(gg), sigmoidf_(bb)};
#pragma unroll
    for (int cc = 0; cc < 3; cc++) {
        float spec = sigmoidf_(feature[i*16 + 13 + cc]);
        float light = out[(size_t)12*N + 3*i + cc];
        float specular = spec * light * gate[cc];
        out[(size_t)9*N + 3*i + cc] = specular;
        out[3*i + cc] = out[(size_t)6*N + 3*i + cc] + specular;
    }
}

// ---------------- launch ----------------
extern "C" void kernel_launch(void* const* d_in, const int* in_sizes, int n_in,
                              void* d_out, int out_size) {
    const float* normals = (const float*)d_in[0];
    const float* viewd   = (const float*)d_in[1];
    const float* feature = (const float*)d_in[2];
    const float* refSH   = (const float*)d_in[3];
    const float* w0 = (const float*)d_in[4];
    const float* b0 = (const float*)d_in[5];
    const float* b1 = (const float*)d_in[7];
    const float* b2 = (const float*)d_in[9];
    const float* b3 = (const float*)d_in[11];
    int N = in_sizes[0] / 3;
    float* out = (float*)d_out;

    __half *act0, *act1, *w1T, *w2T, *w3T, *wcT, *cs;
    float *bcPad;
    cudaGetSymbolAddress((void**)&act0, g_act0);
    cudaGetSymbolAddress((void**)&act1, g_act1);
    cudaGetSymbolAddress((void**)&w1T, g_w1T);
    cudaGetSymbolAddress((void**)&w2T, g_w2T);
    cudaGetSymbolAddress((void**)&w3T, g_w3T);
    cudaGetSymbolAddress((void**)&wcT, g_wcT);
    cudaGetSymbolAddress((void**)&cs,  g_cs);
    cudaGetSymbolAddress((void**)&bcPad, g_bcPad);

    cudaFuncSetAttribute(gemm_uni_kernel, cudaFuncAttributeMaxDynamicSharedMemorySize, G_SMEM);

    setup_consts_kernel<<<1, 1>>>();

    int prepTotal = 3*WDIM*WDIM + 32*WDIM + 32;
    prep_weights_kernel<<<(prepTotal + 255)/256, 256>>>((const float*)d_in[6], (const float*)d_in[8],
                                                        (const float*)d_in[10], (const float*)d_in[12],
                                                        (const float*)d_in[13]);

    physics_kernel<<<N/32, 32>>>(normals, viewd, feature, refSH, out, N);

    layer0_kernel_v3<<<N/64, 256>>>(w0, b0, N);

    dim3 gg(WDIM/128, N/128);
    gemm_uni_kernel<<<gg, 256, G_SMEM>>>(act0, w1T, b1, act1, N);
    gemm_uni_kernel<<<gg, 256, G_SMEM>>>(act1, w2T, b2, act0, N);
    gemm_uni_kernel<<<gg, 256, G_SMEM>>>(act0, w3T, b3, act1, N);

    wc_gemm_kernel<<<dim3(1, N/128), 128>>>(act1, wcT, bcPad, cs, N);

    final_kernel<<<(N + 127)/128, 128>>>(feature, out, N);
}

// round 8
// speedup vs baseline: 1.7217x; 1.0213x over previous
#include <cuda_runtime.h>
#include <cuda_fp16.h>
#include <math.h>
#include <stdint.h>

#define LMAXX 10
#define NPTS  131072
#define WDIM  512

#if defined(__CUDA_ARCH_FEAT_SM103_ALL) || defined(__CUDA_ARCH_FEAT_SM100_ALL) || defined(__CUDA_ARCH_SPECIFIC__)
#define HAS_TCGEN05 1
#else
#define HAS_TCGEN05 0
#endif

// ---------------- device scratch ----------------
__device__ float  g_KTAB[LMAXX+1][LMAXX+1];
__device__ float  g_DFACT[LMAXX+1];
__device__ __half g_act0[NPTS*WDIM];
__device__ __half g_act1[NPTS*WDIM];
__device__ float  g_h0[NPTS*8];
__device__ __half g_w1T[WDIM*WDIM];
__device__ __half g_w2T[WDIM*WDIM];
__device__ __half g_w3T[WDIM*WDIM];
__device__ __half g_wcT[32*WDIM];
__device__ float  g_bcPad[32];

__constant__ float LAMBERT_C[11] = {
    3.1415926535897927f, 2.0943951023931957f, 0.7853981633974483f, 0.0f,
    -0.13089969389957473f, 0.0f, 0.04908738521234052f, 0.0f,
    -0.024543692606170262f, 0.0f, 0.014317154020265985f};

// ---------------- common helpers ----------------
__device__ __forceinline__ uint32_t smem_u32(const void* p) {
    uint32_t a;
    asm("{ .reg .u64 t; cvta.to.shared.u64 t, %1; cvt.u32.u64 %0, t; }" : "=r"(a) : "l"(p));
    return a;
}
__device__ __forceinline__ void cp16(uint32_t smem, const void* g) {
    asm volatile("cp.async.ca.shared.global [%0], [%1], 16;\n" :: "r"(smem), "l"(g));
}
__device__ __forceinline__ void cp_commit() { asm volatile("cp.async.commit_group;\n"); }
__device__ __forceinline__ void cp_wait1()  { asm volatile("cp.async.wait_group 1;\n"); }
__device__ __forceinline__ void cp_wait0()  { asm volatile("cp.async.wait_group 0;\n"); }
#define SW128(o) ((o) ^ (((o) >> 3) & 0x70))

__device__ __forceinline__ void mma16816(float* d, const uint32_t* a, const uint32_t* b) {
    asm volatile(
        "mma.sync.aligned.m16n8k16.row.col.f32.f16.f16.f32 "
        "{%0,%1,%2,%3}, {%4,%5,%6,%7}, {%8,%9}, {%0,%1,%2,%3};\n"
        : "+f"(d[0]), "+f"(d[1]), "+f"(d[2]), "+f"(d[3])
        : "r"(a[0]), "r"(a[1]), "r"(a[2]), "r"(a[3]), "r"(b[0]), "r"(b[1]));
}
#define LDSM_X4(r, addr) \
    asm volatile("ldmatrix.sync.aligned.m8n8.x4.shared.b16 {%0,%1,%2,%3}, [%4];" \
        : "=r"((r)[0]), "=r"((r)[1]), "=r"((r)[2]), "=r"((r)[3]) : "r"(addr))

#if HAS_TCGEN05
__device__ __forceinline__ uint32_t elect1() {
    uint32_t r;
    asm volatile("{\n\t.reg .pred p;\n\telect.sync _|p, 0xFFFFFFFF;\n\tselp.b32 %0,1,0,p;\n\t}" : "=r"(r));
    return r;
}
#define MBAR_INIT(a, c) \
    asm volatile("mbarrier.init.shared.b64 [%0], %1;" :: "r"(a), "r"((uint32_t)(c)) : "memory")
#define MBAR_INVAL(a) \
    asm volatile("mbarrier.inval.shared.b64 [%0];" :: "r"(a) : "memory")
#define MBAR_WAIT(a, ph) do {                                                   \
    uint32_t _m = (a), _p = (ph), _d;                                           \
    asm volatile("{\n\t.reg .pred p;\n\t"                                       \
        "mbarrier.try_wait.parity.acquire.cta.shared::cta.b64 p, [%1], %2;\n\t" \
        "selp.b32 %0,1,0,p;\n\t}" : "=r"(_d) : "r"(_m), "r"(_p) : "memory");    \
    if (!_d) {                                                                  \
        asm volatile("{\n\t.reg .pred P1;\n\t"                                  \
            "WL_%=:\n\t"                                                        \
            "mbarrier.try_wait.parity.acquire.cta.shared::cta.b64 P1, [%0], %1, 0x989680;\n\t" \
            "@P1 bra.uni WD_%=;\n\t"                                            \
            "bra.uni WL_%=;\n\t"                                                \
            "WD_%=:\n\t}" :: "r"(_m), "r"(_p) : "memory");                      \
    }                                                                           \
} while (0)
#define TC_ALLOC(sa, n) \
    asm volatile("tcgen05.alloc.cta_group::1.sync.aligned.shared::cta.b32 [%0], %1;" \
        :: "r"(sa), "r"((uint32_t)(n)) : "memory")
#define TC_DEALLOC(t, n) \
    asm volatile("tcgen05.dealloc.cta_group::1.sync.aligned.b32 %0, %1;" :: "r"(t), "r"((uint32_t)(n)))
#define TC_COMMIT(mb) \
    asm volatile("tcgen05.commit.cta_group::1.mbarrier::arrive::one.shared::cluster.b64 [%0];" \
        :: "r"(mb) : "memory")
#define TC_FENCE_AFTER()  asm volatile("tcgen05.fence::after_thread_sync;" ::: "memory")
#define TC_FENCE_BEFORE() asm volatile("tcgen05.fence::before_thread_sync;" ::: "memory")
#define TC_WAIT_LD()      asm volatile("tcgen05.wait::ld.sync.aligned;" ::: "memory")
#define FENCE_ASYNC_SH()  asm volatile("fence.proxy.async.shared::cta;" ::: "memory")
#define TC_LD_X32(r, ta) \
    asm volatile("tcgen05.ld.sync.aligned.32x32b.x32.b32 " \
        "{%0, %1, %2, %3, %4, %5, %6, %7, %8, %9, %10, %11, %12, %13, %14, %15, " \
        " %16, %17, %18, %19, %20, %21, %22, %23, %24, %25, %26, %27, %28, %29, %30, %31}, [%32];" \
        : "=r"((r)[0]),  "=r"((r)[1]),  "=r"((r)[2]),  "=r"((r)[3]), \
          "=r"((r)[4]),  "=r"((r)[5]),  "=r"((r)[6]),  "=r"((r)[7]), \
          "=r"((r)[8]),  "=r"((r)[9]),  "=r"((r)[10]), "=r"((r)[11]), \
          "=r"((r)[12]), "=r"((r)[13]), "=r"((r)[14]), "=r"((r)[15]), \
          "=r"((r)[16]), "=r"((r)[17]), "=r"((r)[18]), "=r"((r)[19]), \
          "=r"((r)[20]), "=r"((r)[21]), "=r"((r)[22]), "=r"((r)[23]), \
          "=r"((r)[24]), "=r"((r)[25]), "=r"((r)[26]), "=r"((r)[27]), \
          "=r"((r)[28]), "=r"((r)[29]), "=r"((r)[30]), "=r"((r)[31]) \
        : "r"(ta))

__device__ __forceinline__ void mma_f16_ss(uint32_t d, uint64_t ad, uint64_t bd,
                                           uint32_t idesc, uint32_t en) {
    asm volatile("{\n\t.reg .pred p;\n\tsetp.ne.u32 p, %4, 0;\n\t"
        "tcgen05.mma.cta_group::1.kind::f16 [%0], %1, %2, %3, {%5,%5,%5,%5}, p;\n\t}"
        :: "r"(d), "l"(ad), "l"(bd), "r"(idesc), "r"(en), "r"(0u) : "memory");
}
__device__ __forceinline__ uint64_t make_desc_sw128(uint32_t addr) {
    const uint64_t base = (uint64_t(2) << 61) | (uint64_t(1) << 46) |
                          (uint64_t(64) << 32) | (uint64_t(1) << 16);
    return base | ((uint64_t)(addr >> 4) & 0x3FFF);
}
#endif  // HAS_TCGEN05

// ---------------- unified big GEMM (unchanged from R7 fast path) ----------------
#define G_ABUF   (128*128)
#define G_OFFTM  0
#define G_OFFMB  8
#define G_OFFBI  256
#define G_OFFA   1024
#define G_OFFB   (G_OFFA + 3*G_ABUF)
#define G_SMEM   (G_OFFB + 3*G_ABUF)   // 99328

__device__ __forceinline__ void g_load_stage(uint32_t sb, const __half* A, const __half* BT,
                                             long rowbase, int nbase, int tid, int buf, int k0) {
#pragma unroll
    for (int i = 0; i < 4; i++) {
        int t = tid + i * 256;
        int r = t >> 3, c = t & 7;
        uint32_t off = (uint32_t)(r * 128 + c * 16);
        cp16(sb + G_OFFA + buf * G_ABUF + SW128(off), &A[(rowbase + r) * WDIM + k0 + c * 8]);
    }
#pragma unroll
    for (int i = 0; i < 4; i++) {
        int t = tid + i * 256;
        int r = t >> 3, c = t & 7;
        uint32_t off = (uint32_t)(r * 128 + c * 16);
        cp16(sb + G_OFFB + buf * G_ABUF + SW128(off), &BT[(long)(nbase + r) * WDIM + k0 + c * 8]);
    }
    cp_commit();
}

__global__ void __launch_bounds__(256, 2)
gemm_uni_kernel(const __half* __restrict__ A, const __half* __restrict__ BT,
                const float* __restrict__ bias, __half* __restrict__ C, int M) {
    extern __shared__ __align__(1024) char smem[];
    uint32_t sb = smem_u32(smem);
    int tid = threadIdx.x, wid = tid >> 5, lid = tid & 31;
    long rowbase = (long)blockIdx.y * 128;
    int nbase = blockIdx.x * 128;
    float* biasS = (float*)(smem + G_OFFBI);
    for (int i = tid; i < 128; i += 256) biasS[i] = bias[nbase + i];

    constexpr int NS = WDIM / 64;  // 8

#if HAS_TCGEN05
    if (wid == 0) TC_ALLOC(sb + G_OFFTM, 128);
    if (tid == 0) MBAR_INIT(sb + G_OFFMB, 1);
    __syncthreads();
    uint32_t tmem;
    asm volatile("ld.shared.b32 %0, [%1];" : "=r"(tmem) : "r"(sb + G_OFFTM));

    const uint32_t idesc = (1u << 4) | (16u << 17) | (8u << 24);

    g_load_stage(sb, A, BT, rowbase, nbase, tid, 0, 0);
    for (int s = 0; s < NS; s++) {
        int buf = s & 1;
        if (s >= 1) MBAR_WAIT(sb + G_OFFMB, (s - 1) & 1);
        if (s + 1 < NS) { g_load_stage(sb, A, BT, rowbase, nbase, tid, buf ^ 1, (s + 1) * 64); cp_wait1(); }
        else cp_wait0();
        __syncthreads();
        if (wid == 0 && elect1()) {
            FENCE_ASYNC_SH();
            uint64_t ad = make_desc_sw128(sb + G_OFFA + buf * G_ABUF);
            uint64_t bd = make_desc_sw128(sb + G_OFFB + buf * G_ABUF);
#pragma unroll
            for (int k = 0; k < 4; k++)
                mma_f16_ss(tmem, ad + k * 2, bd + k * 2, idesc, (s > 0 || k > 0) ? 1u : 0u);
            TC_COMMIT(sb + G_OFFMB);
        }
    }
    MBAR_WAIT(sb + G_OFFMB, (NS - 1) & 1);
    TC_FENCE_AFTER();

    int sp = wid & 3, ch = wid >> 2;
    uint32_t d[64];
    TC_LD_X32(&d[0],  tmem + ch * 64);
    TC_LD_X32(&d[32], tmem + ch * 64 + 32);
    TC_WAIT_LD();
    TC_FENCE_BEFORE();

    long r = rowbase + sp * 32 + lid;
    __half* crow = C + r * WDIM + nbase + ch * 64;
    const float* bp = biasS + ch * 64;
#pragma unroll
    for (int c0 = 0; c0 < 64; c0 += 8) {
        __half h[8];
#pragma unroll
        for (int j = 0; j < 8; j++)
            h[j] = __float2half(fmaxf(__uint_as_float(d[c0 + j]) + bp[c0 + j], 0.0f));
        *(uint4*)&crow[c0] = *(uint4*)h;
    }
    __syncthreads();
    if (tid == 0) MBAR_INVAL(sb + G_OFFMB);
    __syncthreads();
    if (wid == 0) TC_DEALLOC(tmem, 128);

#else  // ---------------- HMMA fallback: ldmatrix + 3-stage cp.async ring ----------------
    int wm = wid & 3, wn = wid >> 2;
    int g = lid >> 2, t4 = lid & 3;
    int part = lid >> 3, r8 = lid & 7;
    int prow = (part & 1) * 8 + r8;
    int pkb  = (part >> 1) * 16;

    float acc[2][8][4];
#pragma unroll
    for (int a_ = 0; a_ < 2; a_++)
#pragma unroll
        for (int b_ = 0; b_ < 8; b_++)
#pragma unroll
            for (int c_ = 0; c_ < 4; c_++) acc[a_][b_][c_] = 0.0f;

    g_load_stage(sb, A, BT, rowbase, nbase, tid, 0, 0);
    g_load_stage(sb, A, BT, rowbase, nbase, tid, 1, 64);
    for (int s = 0; s < NS; s++) {
        if (s + 1 < NS) cp_wait1(); else cp_wait0();
        __syncthreads();
        if (s + 2 < NS) g_load_stage(sb, A, BT, rowbase, nbase, tid, (s + 2) % 3, (s + 2) * 64);

        int buf = s % 3;
        uint32_t sbA = sb + G_OFFA + buf * G_ABUF;
        uint32_t sbB = sb + G_OFFB + buf * G_ABUF;
#pragma unroll
        for (int kk = 0; kk < 64; kk += 16) {
            uint32_t a[2][4], b[4][4];
#pragma unroll
            for (int sm_ = 0; sm_ < 2; sm_++) {
                int row = wm * 32 + sm_ * 16 + prow;
                uint32_t addr = sbA + SW128((uint32_t)(row * 128 + kk * 2 + pkb));
                LDSM_X4(a[sm_], addr);
            }
#pragma unroll
            for (int j2 = 0; j2 < 4; j2++) {
                int row = wn * 64 + j2 * 16 + prow;
                uint32_t addr = sbB + SW128((uint32_t)(row * 128 + kk * 2 + pkb));
                LDSM_X4(b[j2], addr);
            }
#pragma unroll
            for (int sm_ = 0; sm_ < 2; sm_++) {
#pragma unroll
                for (int j2 = 0; j2 < 4; j2++) {
                    uint32_t blo[2] = {b[j2][0], b[j2][2]};
                    uint32_t bhi[2] = {b[j2][1], b[j2][3]};
                    mma16816(acc[sm_][2 * j2],     a[sm_], blo);
                    mma16816(acc[sm_][2 * j2 + 1], a[sm_], bhi);
                }
            }
        }
    }
    __syncthreads();
#pragma unroll
    for (int sm_ = 0; sm_ < 2; sm_++) {
#pragma unroll
        for (int j = 0; j < 8; j++) {
            long r0 = rowbase + wm * 32 + sm_ * 16 + g;
            int c0 = nbase + wn * 64 + j * 8 + t4 * 2;
            float bx = biasS[c0 - nbase], by = biasS[c0 - nbase + 1];
            float v0 = fmaxf(acc[sm_][j][0] + bx, 0.f);
            float v1 = fmaxf(acc[sm_][j][1] + by, 0.f);
            float v2 = fmaxf(acc[sm_][j][2] + bx, 0.f);
            float v3 = fmaxf(acc[sm_][j][3] + by, 0.f);
            *(__half2*)&C[r0 * WDIM + c0]       = __floats2half2_rn(v0, v1);
            *(__half2*)&C[(r0 + 8) * WDIM + c0] = __floats2half2_rn(v2, v3);
        }
    }
#endif
}

__device__ __forceinline__ float sigmoidf_(float x) { return 1.0f / (1.0f + expf(-x)); }

// ---------------- wc GEMM (N=32) fused with final epilogue ----------------
__global__ void __launch_bounds__(128) wc_final_kernel(
    const __half* __restrict__ A, const __half* __restrict__ BT,
    const float* __restrict__ bias, const float* __restrict__ feature,
    float* __restrict__ out, int N) {
    constexpr int BM = 128, BK = 32, BN = 32, NTH = 128;
    constexpr int LDA = BK + 8;
    __shared__ __half As[2][BM][LDA];
    __shared__ __half Bs[2][BN][LDA];
    __shared__ float cs_s[128][28];
    int tid = threadIdx.x;
    int warp = tid >> 5, lane = tid & 31;
    int wm = warp;
    int g = lane >> 2, t4 = lane & 3;
    long rowbase = (long)blockIdx.y * BM;

    float acc[2][4][4];
#pragma unroll
    for (int a_ = 0; a_ < 2; a_++)
#pragma unroll
        for (int b_ = 0; b_ < 4; b_++)
#pragma unroll
            for (int c_ = 0; c_ < 4; c_++) acc[a_][b_][c_] = 0.0f;

    auto load_stage = [&](int buf, int k0) {
#pragma unroll
        for (int t = tid; t < BM * (BK/8); t += NTH) {
            int r = t >> 2, seg = t & 3;
            cp16(smem_u32(&As[buf][r][seg*8]), &A[(rowbase + r) * WDIM + k0 + seg*8]);
        }
#pragma unroll
        for (int t = tid; t < BN * (BK/8); t += NTH) {
            int r = t >> 2, seg = t & 3;
            cp16(smem_u32(&Bs[buf][r][seg*8]), &BT[(long)r * WDIM + k0 + seg*8]);
        }
        cp_commit();
    };

    constexpr int NS = WDIM / BK;
    load_stage(0, 0);
    for (int s = 0; s < NS; s++) {
        int cur = s & 1;
        if (s + 1 < NS) { load_stage(cur ^ 1, (s + 1) * BK); cp_wait1(); }
        else cp_wait0();
        __syncthreads();
#pragma unroll
        for (int kk = 0; kk < BK; kk += 16) {
            uint32_t a[2][4], b[4][2];
#pragma unroll
            for (int sm_ = 0; sm_ < 2; sm_++) {
                int r = wm*32 + sm_*16;
                a[sm_][0] = *(const uint32_t*)&As[cur][r + g    ][kk + t4*2    ];
                a[sm_][1] = *(const uint32_t*)&As[cur][r + g + 8][kk + t4*2    ];
                a[sm_][2] = *(const uint32_t*)&As[cur][r + g    ][kk + t4*2 + 8];
                a[sm_][3] = *(const uint32_t*)&As[cur][r + g + 8][kk + t4*2 + 8];
            }
#pragma unroll
            for (int j = 0; j < 4; j++) {
                int n = j*8;
                b[j][0] = *(const uint32_t*)&Bs[cur][n + g][kk + t4*2    ];
                b[j][1] = *(const uint32_t*)&Bs[cur][n + g][kk + t4*2 + 8];
            }
#pragma unroll
            for (int sm_ = 0; sm_ < 2; sm_++)
#pragma unroll
                for (int j = 0; j < 4; j++)
                    mma16816(acc[sm_][j], a[sm_], b[j]);
        }
        __syncthreads();
    }

    // stage logits into SMEM (only cols < 27 matter)
#pragma unroll
    for (int sm_ = 0; sm_ < 2; sm_++) {
#pragma unroll
        for (int j = 0; j < 4; j++) {
            int r0 = wm*32 + sm_*16 + g;
            int c0 = j*8 + t4*2;
            if (c0 < 27) {
                cs_s[r0][c0]     = acc[sm_][j][0] + bias[c0];
                cs_s[r0 + 8][c0] = acc[sm_][j][2] + bias[c0];
            }
            if (c0 + 1 < 27) {
                cs_s[r0][c0 + 1]     = acc[sm_][j][1] + bias[c0 + 1];
                cs_s[r0 + 8][c0 + 1] = acc[sm_][j][3] + bias[c0 + 1];
            }
        }
    }
    __syncthreads();

    // final epilogue: one point per thread
    long i = rowbase + tid;
    float coe[9];
#pragma unroll
    for (int k = 0; k < 9; k++) coe[k] = feature[i*16 + 1 + k];
    float rr = 0.f, gg = 0.f, bb = 0.f;
#pragma unroll
    for (int k = 0; k < 9; k++) {
        rr += cs_s[tid][k]      * coe[k];
        gg += cs_s[tid][9 + k]  * coe[k];
        bb += cs_s[tid][18 + k] * coe[k];
    }
    float gate[3] = {sigmoidf_(rr), sigmoidf_(gg), sigmoidf_(bb)};
#pragma unroll
    for (int cc = 0; cc < 3; cc++) {
        float spec = sigmoidf_(feature[i*16 + 13 + cc]);
        float light = out[(size_t)12*N + 3*i + cc];
        float specular = spec * light * gate[cc];
        out[(size_t)9*N + 3*i + cc] = specular;
        out[3*i + cc] = out[(size_t)6*N + 3*i + cc] + specular;
    }
}

// ---------------- weight prep (+ consts, merged) ----------------
__global__ void prep_weights_kernel(const float* __restrict__ w1, const float* __restrict__ w2,
                                    const float* __restrict__ w3, const float* __restrict__ wc,
                                    const float* __restrict__ bc) {
    int idx = blockIdx.x * blockDim.x + threadIdx.x;
    if (idx == 0) {
        double fact[22];
        fact[0] = 1.0;
        for (int i = 1; i <= 21; i++) fact[i] = fact[i-1] * i;
        for (int l = 0; l <= LMAXX; l++)
            for (int m = 0; m <= l; m++) {
                double K = sqrt((2.0*l + 1.0) / (4.0*M_PI) * fact[l-m] / fact[l+m]);
                g_KTAB[l][m] = (float)(m == 0 ? K : sqrt(2.0) * K);
            }
        double df = 1.0;
        g_DFACT[0] = 1.0f;
        for (int m = 1; m <= LMAXX; m++) { df *= (2.0*m - 1.0); g_DFACT[m] = (float)df; }
    }
    const int NW = 3 * WDIM * WDIM;
    if (idx < NW) {
        int which = idx >> 18;
        int r = idx & (WDIM*WDIM - 1);
        int k = r >> 9, n = r & 511;
        const float* w = (which == 0) ? w1 : (which == 1) ? w2 : w3;
        __half* o = (which == 0) ? g_w1T : (which == 1) ? g_w2T : g_w3T;
        o[n*WDIM + k] = __float2half(w[k*WDIM + n]);
    } else if (idx < NW + 32*WDIM) {
        int r = idx - NW;
        int k = r & 511, n = r >> 9;
        g_wcT[n*WDIM + k] = __float2half(n < 27 ? wc[k*27 + n] : 0.0f);
    } else if (idx < NW + 32*WDIM + 32) {
        int n = idx - (NW + 32*WDIM);
        g_bcPad[n] = n < 27 ? bc[n] : 0.0f;
    }
}

// ---------------- physics: fused dual SH accumulation, unit directions ----------------
__global__ void physics_kernel(const float* __restrict__ normals,
                               const float* __restrict__ viewd,
                               const float* __restrict__ feature,
                               const float* __restrict__ refSH,
                               float* __restrict__ out, int N) {
    __shared__ float ss[32 * 363];
    int lane = threadIdx.x;
    int base = blockIdx.x * 32;
    int i = base + lane;

    const float4* src = (const float4*)(refSH + (size_t)base * 363);
    float4* dst = (float4*)ss;
    for (int t = lane; t < (32*363)/4; t += 32) dst[t] = src[t];
    __syncwarp();

    float nx = normals[i*3+0], ny = normals[i*3+1], nz = normals[i*3+2];
    float vx = viewd[i*3+0],   vy = viewd[i*3+1],   vz = viewd[i*3+2];
    float f0 = feature[i*16];
    float rough = fmaxf(f0, 0.0f) + log1pf(expf(-fabsf(f0)));
    float dotnv = nx*vx + ny*vy + nz*vz;
    // |n|=|v|=1 (inputs normalized) => |w|=1 as well; r==1 so all r^l terms vanish.
    float wx = 2.0f*nx*dotnv - vx;
    float wy = 2.0f*ny*dotnv - vy;
    float wz = 2.0f*nz*dotnv - vz;

    const float* row = ss + lane * 363;

    // azimuthal recurrences for both directions
    float cA[LMAXX+1], sA[LMAXX+1], cB[LMAXX+1], sB[LMAXX+1];
    cA[0] = 1.0f; sA[0] = 0.0f; cB[0] = 1.0f; sB[0] = 0.0f;
#pragma unroll
    for (int m = 1; m <= LMAXX; m++) {
        cA[m] = nx*cA[m-1] - ny*sA[m-1];
        sA[m] = nx*sA[m-1] + ny*cA[m-1];
        cB[m] = wx*cB[m-1] - wy*sB[m-1];
        sB[m] = wx*sB[m-1] + wy*cB[m-1];
    }
    float wlB[LMAXX+1];
#pragma unroll
    for (int l = 0; l <= LMAXX; l++) wlB[l] = expf(-(float)(l*(l+1)) * 0.5f * rough);

    float aI[3] = {0.f,0.f,0.f}, aL[3] = {0.f,0.f,0.f};

#pragma unroll
    for (int m = 0; m <= LMAXX; m++) {
        float QAa = g_DFACT[m], QBa = QAa;    // Q[m][m] direction-independent
        {
            float kw = g_KTAB[m][m];
            float fA = kw * QAa * LAMBERT_C[m];
            float fB = kw * QBa * wlB[m];
            int b = (m*m + m) * 3;
            if (m == 0) {
#pragma unroll
                for (int cc = 0; cc < 3; cc++) {
                    float rv = row[b+cc];
                    aI[cc] += fA*rv; aL[cc] += fB*rv;
                }
            } else {
                float pA = fA*cA[m], qA = fA*sA[m];
                float pB = fB*cB[m], qB = fB*sB[m];
#pragma unroll
                for (int cc = 0; cc < 3; cc++) {
                    float rp_ = row[b+3*m+cc], rm_ = row[b-3*m+cc];
                    aI[cc] += pA*rp_ + qA*rm_;
                    aL[cc] += pB*rp_ + qB*rm_;
                }
            }
        }
        if (m < LMAXX) {
            float QAb = (2.0f*m + 1.0f) * nz * QAa;
            float QBb = (2.0f*m + 1.0f) * wz * QBa;
            {
                int l = m + 1;
                float kw = g_KTAB[l][m];
                float fA = kw * QAb * LAMBERT_C[l];
                float fB = kw * QBb * wlB[l];
                int b = (l*l + l) * 3;
                if (m == 0) {
#pragma unroll
                    for (int cc = 0; cc < 3; cc++) {
                        float rv = row[b+cc];
                        aI[cc] += fA*rv; aL[cc] += fB*rv;
                    }
                } else {
                    float pA = fA*cA[m], qA = fA*sA[m];
                    float pB = fB*cB[m], qB = fB*sB[m];
#pragma unroll
                    for (int cc = 0; cc < 3; cc++) {
                        float rp_ = row[b+3*m+cc], rm_ = row[b-3*m+cc];
                        aI[cc] += pA*rp_ + qA*rm_;
                        aL[cc] += pB*rp_ + qB*rm_;
                    }
                }
            }
#pragma unroll
            for (int l = m + 2; l <= LMAXX; l++) {
                float inv_lm = 1.0f / (float)(l - m);
                float c1 = (2.0f*l - 1.0f), c2 = (float)(l + m - 1);
                float QAc = (c1 * nz * QAb - c2 * QAa) * inv_lm;
                float QBc = (c1 * wz * QBb - c2 * QBa) * inv_lm;
                QAa = QAb; QAb = QAc;
                QBa = QBb; QBb = QBc;
                float kw = g_KTAB[l][m];
                float fA = kw * QAc * LAMBERT_C[l];
                float fB = kw * QBc * wlB[l];
                int b = (l*l + l) * 3;
                if (m == 0) {
#pragma unroll
                    for (int cc = 0; cc < 3; cc++) {
                        float rv = row[b+cc];
                        aI[cc] += fA*rv; aL[cc] += fB*rv;
                    }
                } else {
                    float pA = fA*cA[m], qA = fA*sA[m];
                    float pB = fB*cB[m], qB = fB*sB[m];
#pragma unroll
                    for (int cc = 0; cc < 3; cc++) {
                        float rp_ = row[b+3*m+cc], rm_ = row[b-3*m+cc];
                        aI[cc] += pA*rp_ + qA*rm_;
                        aL[cc] += pB*rp_ + qB*rm_;
                    }
                }
            }
        }
    }

#pragma unroll
    for (int cc = 0; cc < 3; cc++) {
        float ir = fmaxf(aI[cc], 0.0f);
        float li = fmaxf(aL[cc], 0.0f);
        float alb = sigmoidf_(feature[i*16 + 10 + cc]);
        out[(size_t)3*N  + 3*i + cc] = alb;
        out[(size_t)6*N  + 3*i + cc] = alb * ir;
        out[(size_t)12*N + 3*i + cc] = li;
        out[(size_t)15*N + 3*i + cc] = ir;
    }
    float* h = g_h0 + (size_t)i * 8;
    h[0] = dotnv; h[1] = vx; h[2] = vy; h[3] = vz;
    h[4] = nx; h[5] = ny; h[6] = nz; h[7] = rough;
}

// ---------------- layer0 v3 ----------------
__global__ void __launch_bounds__(256) layer0_kernel_v3(
    const float* __restrict__ w0, const float* __restrict__ b0, int N) {
    __shared__ float sw[8 * WDIM];
    __shared__ float sbias[WDIM];
    __shared__ float sh[64 * 8];
    int tid = threadIdx.x;
    long base = (long)blockIdx.x * 64;

    for (int i = tid; i < 8 * WDIM; i += 256) sw[i] = w0[i];
    for (int i = tid; i < WDIM; i += 256) sbias[i] = b0[i];
    for (int i = tid; i < 64 * 8 / 4; i += 256)
        ((float4*)sh)[i] = ((const float4*)(g_h0 + base * 8))[i];
    __syncthreads();

    int c0 = (tid & 127) * 4;
    int rg = tid >> 7;

    float w[8][4], bb[4];
#pragma unroll
    for (int j = 0; j < 8; j++)
#pragma unroll
        for (int i = 0; i < 4; i++) w[j][i] = sw[j * WDIM + c0 + i];
#pragma unroll
    for (int i = 0; i < 4; i++) bb[i] = sbias[c0 + i];

    for (int r = rg; r < 64; r += 2) {
        const float* hh = sh + r * 8;
        __half res[4];
#pragma unroll
        for (int i = 0; i < 4; i++) {
            float acc = bb[i];
#pragma unroll
            for (int j = 0; j < 8; j++) acc += hh[j] * w[j][i];
            res[i] = __float2half(fmaxf(acc, 0.0f));
        }
        *(uint2*)&g_act0[(base + r) * WDIM + c0] = *(uint2*)res;
    }
}

// ---------------- launch ----------------
extern "C" void kernel_launch(void* const* d_in, const int* in_sizes, int n_in,
                              void* d_out, int out_size) {
    const float* normals = (const float*)d_in[0];
    const float* viewd   = (const float*)d_in[1];
    const float* feature = (const float*)d_in[2];
    const float* refSH   = (const float*)d_in[3];
    const float* w0 = (const float*)d_in[4];
    const float* b0 = (const float*)d_in[5];
    const float* b1 = (const float*)d_in[7];
    const float* b2 = (const float*)d_in[9];
    const float* b3 = (const float*)d_in[11];
    int N = in_sizes[0] / 3;
    float* out = (float*)d_out;

    __half *act0, *act1, *w1T, *w2T, *w3T, *wcT;
    float *bcPad;
    cudaGetSymbolAddress((void**)&act0, g_act0);
    cudaGetSymbolAddress((void**)&act1, g_act1);
    cudaGetSymbolAddress((void**)&w1T, g_w1T);
    cudaGetSymbolAddress((void**)&w2T, g_w2T);
    cudaGetSymbolAddress((void**)&w3T, g_w3T);
    cudaGetSymbolAddress((void**)&wcT, g_wcT);
    cudaGetSymbolAddress((void**)&bcPad, g_bcPad);

    cudaFuncSetAttribute(gemm_uni_kernel, cudaFuncAttributeMaxDynamicSharedMemorySize, G_SMEM);

    int prepTotal = 3*WDIM*WDIM + 32*WDIM + 32;
    prep_weights_kernel<<<(prepTotal + 255)/256, 256>>>((const float*)d_in[6], (const float*)d_in[8],
                                                        (const float*)d_in[10], (const float*)d_in[12],
                                                        (const float*)d_in[13]);

    physics_kernel<<<N/32, 32>>>(normals, viewd, feature, refSH, out, N);

    layer0_kernel_v3<<<N/64, 256>>>(w0, b0, N);

    dim3 gg(WDIM/128, N/128);
    gemm_uni_kernel<<<gg, 256, G_SMEM>>>(act0, w1T, b1, act1, N);
    gemm_uni_kernel<<<gg, 256, G_SMEM>>>(act1, w2T, b2, act0, N);
    gemm_uni_kernel<<<gg, 256, G_SMEM>>>(act0, w3T, b3, act1, N);

    wc_final_kernel<<<dim3(1, N/128), 128>>>(act1, wcT, bcPad, feature, out, N);
}